// round 1
// baseline (speedup 1.0000x reference)
#include <cuda_runtime.h>
#include <math_constants.h>
#include <cstdint>
#include <cstddef>

// Problem constants
#define BATCH 4
#define NH    16
#define SEQ   2048
#define DH    128
#define DM    2048           // NH*DH
#define MROWS (BATCH*SEQ)    // 8192

#define TSA 136              // padded smem stride for transposed K-major tiles

// ---------------------------------------------------------------------------
// Device scratch (static globals; no runtime allocation allowed)
// ---------------------------------------------------------------------------
__device__ float g_Q[(size_t)BATCH * NH * SEQ * DH];   // 67 MB
__device__ float g_K[(size_t)BATCH * NH * SEQ * DH];   // 67 MB
__device__ float g_V[(size_t)BATCH * NH * SEQ * DH];   // 67 MB
__device__ float g_AO[(size_t)BATCH * SEQ * DM];       // 67 MB
__device__ float g_P[(size_t)BATCH * NH * SEQ * SEQ];  // 1 GiB (probs scratch when
                                                       // attn_weights not in d_out)

// ---------------------------------------------------------------------------
// Shared 128x128x16 FFMA tile compute (8x8 per thread, 256 threads)
// ---------------------------------------------------------------------------
template <int LDB>
__device__ __forceinline__ void compute_tile(const float (*As)[TSA],
                                             const float (*Bs)[LDB],
                                             int ty, int tx,
                                             float (&acc)[8][8]) {
#pragma unroll
    for (int kk = 0; kk < 16; kk++) {
        float a[8], b[8];
#pragma unroll
        for (int j = 0; j < 8; j++) a[j] = As[kk][ty * 8 + j];
#pragma unroll
        for (int j = 0; j < 8; j++) b[j] = Bs[kk][tx * 8 + j];
#pragma unroll
        for (int i = 0; i < 8; i++)
#pragma unroll
            for (int j = 0; j < 8; j++)
                acc[i][j] = fmaf(a[i], b[j], acc[i][j]);
    }
}

// ---------------------------------------------------------------------------
// Kernel 1: QKV projection. C[n,o] = sum_d X[n,d] * W[o,d]  (NT GEMM)
// Output written in [B, H, S, Dh] layout. which: 0=Q, 1=K, 2=V.
// ---------------------------------------------------------------------------
__global__ void __launch_bounds__(256, 2)
gemm_proj_kernel(const float* __restrict__ X, const float* __restrict__ W, int which) {
    __shared__ float As[16][TSA];
    __shared__ float Bs[16][TSA];

    const int tid = threadIdx.x;
    const int tx = tid & 15, ty = tid >> 4;
    const int m0 = blockIdx.y * 128;
    const int n0 = blockIdx.x * 128;

    const int r0 = tid >> 2;          // 0..63
    const int r1 = r0 + 64;           // 64..127
    const int c4 = (tid & 3) * 4;     // 0,4,8,12

    float acc[8][8];
#pragma unroll
    for (int i = 0; i < 8; i++)
#pragma unroll
        for (int j = 0; j < 8; j++) acc[i][j] = 0.f;

    float4 ra0 = *(const float4*)(X + (size_t)(m0 + r0) * DM + c4);
    float4 ra1 = *(const float4*)(X + (size_t)(m0 + r1) * DM + c4);
    float4 rb0 = *(const float4*)(W + (size_t)(n0 + r0) * DM + c4);
    float4 rb1 = *(const float4*)(W + (size_t)(n0 + r1) * DM + c4);

    const int KT = DM / 16;
    for (int kt = 1; kt <= KT; kt++) {
        // store staged regs -> smem
        As[c4 + 0][r0] = ra0.x; As[c4 + 1][r0] = ra0.y; As[c4 + 2][r0] = ra0.z; As[c4 + 3][r0] = ra0.w;
        As[c4 + 0][r1] = ra1.x; As[c4 + 1][r1] = ra1.y; As[c4 + 2][r1] = ra1.z; As[c4 + 3][r1] = ra1.w;
        Bs[c4 + 0][r0] = rb0.x; Bs[c4 + 1][r0] = rb0.y; Bs[c4 + 2][r0] = rb0.z; Bs[c4 + 3][r0] = rb0.w;
        Bs[c4 + 0][r1] = rb1.x; Bs[c4 + 1][r1] = rb1.y; Bs[c4 + 2][r1] = rb1.z; Bs[c4 + 3][r1] = rb1.w;
        __syncthreads();
        if (kt < KT) {
            const int k0 = kt * 16;
            ra0 = *(const float4*)(X + (size_t)(m0 + r0) * DM + k0 + c4);
            ra1 = *(const float4*)(X + (size_t)(m0 + r1) * DM + k0 + c4);
            rb0 = *(const float4*)(W + (size_t)(n0 + r0) * DM + k0 + c4);
            rb1 = *(const float4*)(W + (size_t)(n0 + r1) * DM + k0 + c4);
        }
        compute_tile<TSA>(As, Bs, ty, tx, acc);
        __syncthreads();
    }

    float* Gout = (which == 0) ? g_Q : (which == 1) ? g_K : g_V;
    const int h = blockIdx.x;     // tile width 128 == head width
    const int dh0 = tx * 8;
#pragma unroll
    for (int i = 0; i < 8; i++) {
        const int row = m0 + ty * 8 + i;
        const int b = row >> 11;
        const int s = row & (SEQ - 1);
        float* dst = Gout + ((size_t)(b * NH + h) * SEQ + s) * DH + dh0;
        *(float4*)(dst + 0) = make_float4(acc[i][0], acc[i][1], acc[i][2], acc[i][3]);
        *(float4*)(dst + 4) = make_float4(acc[i][4], acc[i][5], acc[i][6], acc[i][7]);
    }
}

// ---------------------------------------------------------------------------
// Kernel 2: scores = Q @ K^T per (b,h). Causal: skip tiles fully above diag.
// grid: (bj=16, bi=16, bh=64)
// ---------------------------------------------------------------------------
__global__ void __launch_bounds__(256, 2)
scores_kernel(float* __restrict__ Pext, int use_ext) {
    const int bj = blockIdx.x;    // key tile
    const int bi = blockIdx.y;    // query tile
    if (bj > bi) return;          // fully masked tile
    const int bh = blockIdx.z;

    float* P = use_ext ? Pext : g_P;
    const float* A = g_Q + (size_t)bh * SEQ * DH;
    const float* B = g_K + (size_t)bh * SEQ * DH;

    __shared__ float As[16][TSA];
    __shared__ float Bs[16][TSA];

    const int tid = threadIdx.x;
    const int tx = tid & 15, ty = tid >> 4;
    const int m0 = bi * 128;
    const int n0 = bj * 128;
    const int r0 = tid >> 2;
    const int r1 = r0 + 64;
    const int c4 = (tid & 3) * 4;

    float acc[8][8];
#pragma unroll
    for (int i = 0; i < 8; i++)
#pragma unroll
        for (int j = 0; j < 8; j++) acc[i][j] = 0.f;

    float4 ra0 = *(const float4*)(A + (size_t)(m0 + r0) * DH + c4);
    float4 ra1 = *(const float4*)(A + (size_t)(m0 + r1) * DH + c4);
    float4 rb0 = *(const float4*)(B + (size_t)(n0 + r0) * DH + c4);
    float4 rb1 = *(const float4*)(B + (size_t)(n0 + r1) * DH + c4);

    const int KT = DH / 16;   // 8
    for (int kt = 1; kt <= KT; kt++) {
        As[c4 + 0][r0] = ra0.x; As[c4 + 1][r0] = ra0.y; As[c4 + 2][r0] = ra0.z; As[c4 + 3][r0] = ra0.w;
        As[c4 + 0][r1] = ra1.x; As[c4 + 1][r1] = ra1.y; As[c4 + 2][r1] = ra1.z; As[c4 + 3][r1] = ra1.w;
        Bs[c4 + 0][r0] = rb0.x; Bs[c4 + 1][r0] = rb0.y; Bs[c4 + 2][r0] = rb0.z; Bs[c4 + 3][r0] = rb0.w;
        Bs[c4 + 0][r1] = rb1.x; Bs[c4 + 1][r1] = rb1.y; Bs[c4 + 2][r1] = rb1.z; Bs[c4 + 3][r1] = rb1.w;
        __syncthreads();
        if (kt < KT) {
            const int k0 = kt * 16;
            ra0 = *(const float4*)(A + (size_t)(m0 + r0) * DH + k0 + c4);
            ra1 = *(const float4*)(A + (size_t)(m0 + r1) * DH + k0 + c4);
            rb0 = *(const float4*)(B + (size_t)(n0 + r0) * DH + k0 + c4);
            rb1 = *(const float4*)(B + (size_t)(n0 + r1) * DH + k0 + c4);
        }
        compute_tile<TSA>(As, Bs, ty, tx, acc);
        __syncthreads();
    }

    float* Pp = P + (size_t)bh * SEQ * SEQ;
#pragma unroll
    for (int i = 0; i < 8; i++) {
        const int row = m0 + ty * 8 + i;
        float* dst = Pp + (size_t)row * SEQ + n0 + tx * 8;
        *(float4*)(dst + 0) = make_float4(acc[i][0], acc[i][1], acc[i][2], acc[i][3]);
        *(float4*)(dst + 4) = make_float4(acc[i][4], acc[i][5], acc[i][6], acc[i][7]);
    }
}

// ---------------------------------------------------------------------------
// Kernel 3: row softmax with causal mask. One block per row, whole row in regs.
// Masked positions (j > q) are written as exact 0 (matches softmax(NEG)).
// ---------------------------------------------------------------------------
__device__ __forceinline__ float warp_max(float v) {
#pragma unroll
    for (int o = 16; o > 0; o >>= 1) v = fmaxf(v, __shfl_xor_sync(0xffffffffu, v, o));
    return v;
}
__device__ __forceinline__ float warp_sum(float v) {
#pragma unroll
    for (int o = 16; o > 0; o >>= 1) v += __shfl_xor_sync(0xffffffffu, v, o);
    return v;
}

__global__ void __launch_bounds__(256)
softmax_kernel(float* __restrict__ Pext, int use_ext) {
    __shared__ float shm[8];
    __shared__ float shs[8];
    float* P = use_ext ? Pext : g_P;

    const size_t row = blockIdx.x;
    const int q = (int)(row & (SEQ - 1));
    float* pr = P + row * (size_t)SEQ;
    const int tid = threadIdx.x;
    const int wid = tid >> 5, lid = tid & 31;

    float v[8];
    float m = -CUDART_INF_F;
#pragma unroll
    for (int k = 0; k < 8; k++) {
        const int j = tid + k * 256;
        v[k] = (j <= q) ? pr[j] : -CUDART_INF_F;
        m = fmaxf(m, v[k]);
    }
    m = warp_max(m);
    if (lid == 0) shm[wid] = m;
    __syncthreads();
    if (tid < 32) {
        float t = (tid < 8) ? shm[tid] : -CUDART_INF_F;
        t = warp_max(t);
        if (tid == 0) shm[0] = t;
    }
    __syncthreads();
    m = shm[0];

    float s = 0.f;
#pragma unroll
    for (int k = 0; k < 8; k++) {
        const float e = expf(v[k] - m);   // expf(-inf - m) == 0 for masked
        v[k] = e;
        s += e;
    }
    s = warp_sum(s);
    if (lid == 0) shs[wid] = s;
    __syncthreads();
    if (tid < 32) {
        float t = (tid < 8) ? shs[tid] : 0.f;
        t = warp_sum(t);
        if (tid == 0) shs[0] = t;
    }
    __syncthreads();
    const float inv = 1.f / shs[0];

#pragma unroll
    for (int k = 0; k < 8; k++) pr[tid + k * 256] = v[k] * inv;
}

// ---------------------------------------------------------------------------
// Kernel 4: AV = P @ V per (b,h) (NN GEMM), causal-truncated K loop.
// Output written directly in [B, S, D] layout (g_AO).
// grid: (bi=16, bh=64)
// ---------------------------------------------------------------------------
__global__ void __launch_bounds__(256, 2)
av_kernel(const float* __restrict__ Pext, int use_ext) {
    const int bi = blockIdx.x;
    const int bh = blockIdx.y;

    const float* P = use_ext ? Pext : (const float*)g_P;
    const float* A = P + (size_t)bh * SEQ * SEQ;     // [SEQ, SEQ], k contiguous
    const float* B = g_V + (size_t)bh * SEQ * DH;    // [SEQ, DH],  n contiguous (NN)

    __shared__ float As[16][TSA];
    __shared__ float Bs[16][128];

    const int tid = threadIdx.x;
    const int tx = tid & 15, ty = tid >> 4;
    const int m0 = bi * 128;

    const int r0 = tid >> 2;           // A-tile rows
    const int r1 = r0 + 64;
    const int c4 = (tid & 3) * 4;

    const int br0 = tid >> 5;          // B-tile rows (k), 0..7
    const int br1 = br0 + 8;
    const int bc = (tid & 31) * 4;     // B-tile cols (n)

    float acc[8][8];
#pragma unroll
    for (int i = 0; i < 8; i++)
#pragma unroll
        for (int j = 0; j < 8; j++) acc[i][j] = 0.f;

    float4 ra0 = *(const float4*)(A + (size_t)(m0 + r0) * SEQ + c4);
    float4 ra1 = *(const float4*)(A + (size_t)(m0 + r1) * SEQ + c4);
    float4 rb0 = *(const float4*)(B + (size_t)br0 * DH + bc);
    float4 rb1 = *(const float4*)(B + (size_t)br1 * DH + bc);

    const int KT = (bi + 1) * 8;       // only k-tiles up to (and incl.) diagonal
    for (int kt = 1; kt <= KT; kt++) {
        As[c4 + 0][r0] = ra0.x; As[c4 + 1][r0] = ra0.y; As[c4 + 2][r0] = ra0.z; As[c4 + 3][r0] = ra0.w;
        As[c4 + 0][r1] = ra1.x; As[c4 + 1][r1] = ra1.y; As[c4 + 2][r1] = ra1.z; As[c4 + 3][r1] = ra1.w;
        *(float4*)&Bs[br0][bc] = rb0;
        *(float4*)&Bs[br1][bc] = rb1;
        __syncthreads();
        if (kt < KT) {
            const int k0 = kt * 16;
            ra0 = *(const float4*)(A + (size_t)(m0 + r0) * SEQ + k0 + c4);
            ra1 = *(const float4*)(A + (size_t)(m0 + r1) * SEQ + k0 + c4);
            rb0 = *(const float4*)(B + (size_t)(k0 + br0) * DH + bc);
            rb1 = *(const float4*)(B + (size_t)(k0 + br1) * DH + bc);
        }
        compute_tile<128>(As, Bs, ty, tx, acc);
        __syncthreads();
    }

    const int b = bh >> 4;
    const int h = bh & 15;
#pragma unroll
    for (int i = 0; i < 8; i++) {
        const int row = m0 + ty * 8 + i;
        float* dst = g_AO + (size_t)(b * SEQ + row) * DM + h * DH + tx * 8;
        *(float4*)(dst + 0) = make_float4(acc[i][0], acc[i][1], acc[i][2], acc[i][3]);
        *(float4*)(dst + 4) = make_float4(acc[i][4], acc[i][5], acc[i][6], acc[i][7]);
    }
}

// ---------------------------------------------------------------------------
// Kernel 5: out = AO @ Wo^T + bo  (NT GEMM + bias) into d_out
// ---------------------------------------------------------------------------
__global__ void __launch_bounds__(256, 2)
gemm_outproj_kernel(const float* __restrict__ W, const float* __restrict__ bias,
                    float* __restrict__ Out) {
    __shared__ float As[16][TSA];
    __shared__ float Bs[16][TSA];

    const float* A = g_AO;
    const int tid = threadIdx.x;
    const int tx = tid & 15, ty = tid >> 4;
    const int m0 = blockIdx.y * 128;
    const int n0 = blockIdx.x * 128;
    const int r0 = tid >> 2;
    const int r1 = r0 + 64;
    const int c4 = (tid & 3) * 4;

    float acc[8][8];
#pragma unroll
    for (int i = 0; i < 8; i++)
#pragma unroll
        for (int j = 0; j < 8; j++) acc[i][j] = 0.f;

    float4 ra0 = *(const float4*)(A + (size_t)(m0 + r0) * DM + c4);
    float4 ra1 = *(const float4*)(A + (size_t)(m0 + r1) * DM + c4);
    float4 rb0 = *(const float4*)(W + (size_t)(n0 + r0) * DM + c4);
    float4 rb1 = *(const float4*)(W + (size_t)(n0 + r1) * DM + c4);

    const int KT = DM / 16;
    for (int kt = 1; kt <= KT; kt++) {
        As[c4 + 0][r0] = ra0.x; As[c4 + 1][r0] = ra0.y; As[c4 + 2][r0] = ra0.z; As[c4 + 3][r0] = ra0.w;
        As[c4 + 0][r1] = ra1.x; As[c4 + 1][r1] = ra1.y; As[c4 + 2][r1] = ra1.z; As[c4 + 3][r1] = ra1.w;
        Bs[c4 + 0][r0] = rb0.x; Bs[c4 + 1][r0] = rb0.y; Bs[c4 + 2][r0] = rb0.z; Bs[c4 + 3][r0] = rb0.w;
        Bs[c4 + 0][r1] = rb1.x; Bs[c4 + 1][r1] = rb1.y; Bs[c4 + 2][r1] = rb1.z; Bs[c4 + 3][r1] = rb1.w;
        __syncthreads();
        if (kt < KT) {
            const int k0 = kt * 16;
            ra0 = *(const float4*)(A + (size_t)(m0 + r0) * DM + k0 + c4);
            ra1 = *(const float4*)(A + (size_t)(m0 + r1) * DM + k0 + c4);
            rb0 = *(const float4*)(W + (size_t)(n0 + r0) * DM + k0 + c4);
            rb1 = *(const float4*)(W + (size_t)(n0 + r1) * DM + k0 + c4);
        }
        compute_tile<TSA>(As, Bs, ty, tx, acc);
        __syncthreads();
    }

    const int col0 = n0 + tx * 8;
    float bv[8];
#pragma unroll
    for (int j = 0; j < 8; j++) bv[j] = bias[col0 + j];
#pragma unroll
    for (int i = 0; i < 8; i++) {
        const int row = m0 + ty * 8 + i;
        float* dst = Out + (size_t)row * DM + col0;
        *(float4*)(dst + 0) = make_float4(acc[i][0] + bv[0], acc[i][1] + bv[1],
                                          acc[i][2] + bv[2], acc[i][3] + bv[3]);
        *(float4*)(dst + 4) = make_float4(acc[i][4] + bv[4], acc[i][5] + bv[5],
                                          acc[i][6] + bv[6], acc[i][7] + bv[7]);
    }
}

// ---------------------------------------------------------------------------
// Launch
// ---------------------------------------------------------------------------
extern "C" void kernel_launch(void* const* d_in, const int* in_sizes, int n_in,
                              void* d_out, int out_size) {
    const float* hs = (const float*)d_in[0];
    const float* wq = (const float*)d_in[1];
    const float* wk = (const float*)d_in[2];
    const float* wv = (const float*)d_in[3];
    const float* wo = (const float*)d_in[4];
    const float* bo = (const float*)d_in[5];
    float* out = (float*)d_out;

    const long long OUT_ELEMS = (long long)BATCH * SEQ * DM;        // 16,777,216
    const long long WEI_ELEMS = (long long)BATCH * NH * SEQ * SEQ;  // 268,435,456
    const int use_ext = ((long long)out_size >= OUT_ELEMS + WEI_ELEMS) ? 1 : 0;
    float* Pext = use_ext ? (out + OUT_ELEMS) : nullptr;

    const dim3 blk(256);
    gemm_proj_kernel<<<dim3(16, 64), blk>>>(hs, wq, 0);
    gemm_proj_kernel<<<dim3(16, 64), blk>>>(hs, wk, 1);
    gemm_proj_kernel<<<dim3(16, 64), blk>>>(hs, wv, 2);
    scores_kernel<<<dim3(16, 16, 64), blk>>>(Pext, use_ext);
    softmax_kernel<<<BATCH * NH * SEQ, blk>>>(Pext, use_ext);
    av_kernel<<<dim3(16, 64), blk>>>(Pext, use_ext);
    gemm_outproj_kernel<<<dim3(16, 64), blk>>>(wo, bo, out);
}

// round 5
// speedup vs baseline: 2.4659x; 2.4659x over previous
#include <cuda_runtime.h>
#include <cuda_bf16.h>
#include <math_constants.h>
#include <cstdint>
#include <cstddef>

#define BATCH 4
#define NH    16
#define SEQ   2048
#define DH    128
#define DM    2048
#define BH    (BATCH*NH)     // 64
#define MROWS (BATCH*SEQ)    // 8192

typedef __nv_bfloat16 bf16;

// ---------------------------------------------------------------------------
// Device scratch (static globals; total ~1.66 GB, must stay < 2 GB for x86 link)
// ---------------------------------------------------------------------------
__device__ bf16 g_Hh[(size_t)MROWS * DM];                  // 32 MB
__device__ bf16 g_Hm[(size_t)MROWS * DM];                  // 32 MB
__device__ bf16 g_Wh4[4][(size_t)DM * DM];                 // 128 MB
__device__ bf16 g_Wm4[4][(size_t)DM * DM];                 // 128 MB
__device__ bf16 g_Qh[(size_t)BH * SEQ * DH];               // 32 MB each
__device__ bf16 g_Qm[(size_t)BH * SEQ * DH];
__device__ bf16 g_Kh[(size_t)BH * SEQ * DH];
__device__ bf16 g_Km[(size_t)BH * SEQ * DH];
__device__ bf16 g_Vh[(size_t)BH * SEQ * DH];
__device__ bf16 g_Vm[(size_t)BH * SEQ * DH];
__device__ bf16 g_Vth[(size_t)BH * DH * SEQ];              // 32 MB
__device__ bf16 g_Vtm[(size_t)BH * DH * SEQ];              // 32 MB
// g_S: 1 GiB. Holds fp32 scores; after softmax each 8KB row is overwritten
// IN PLACE with bf16 splits: h at bf16 offsets [0,2048), m at [2048,4096).
__device__ float g_S[(size_t)BH * SEQ * SEQ];
__device__ bf16 g_AOh[(size_t)MROWS * DM];                 // 32 MB
__device__ bf16 g_AOm[(size_t)MROWS * DM];                 // 32 MB

// ---------------------------------------------------------------------------
// PTX helpers (sm_80-era: mma.sync / ldmatrix / cp.async — valid on sm_100)
// ---------------------------------------------------------------------------
__device__ __forceinline__ uint32_t smem_u32(const void* p) {
    uint32_t a;
    asm("{ .reg .u64 t; cvta.to.shared.u64 t, %1; cvt.u32.u64 %0, t; }"
        : "=r"(a) : "l"(p));
    return a;
}

#define LDSM_X4(R, addr) \
    asm volatile("ldmatrix.sync.aligned.m8n8.x4.shared.b16 {%0,%1,%2,%3}, [%4];" \
                 : "=r"((R)[0]), "=r"((R)[1]), "=r"((R)[2]), "=r"((R)[3]) : "r"(addr))

__device__ __forceinline__ void mma_bf16(float* c, const uint32_t* a,
                                         uint32_t b0, uint32_t b1) {
    asm volatile(
        "mma.sync.aligned.m16n8k16.row.col.f32.bf16.bf16.f32 "
        "{%0,%1,%2,%3}, {%4,%5,%6,%7}, {%8,%9}, {%0,%1,%2,%3};"
        : "+f"(c[0]), "+f"(c[1]), "+f"(c[2]), "+f"(c[3])
        : "r"(a[0]), "r"(a[1]), "r"(a[2]), "r"(a[3]), "r"(b0), "r"(b1));
}

__device__ __forceinline__ void cp16(uint32_t s, const void* g) {
    asm volatile("cp.async.cg.shared.global [%0], [%1], 16;" :: "r"(s), "l"(g));
}
#define CP_COMMIT() asm volatile("cp.async.commit_group;" ::: "memory")
#define CP_WAIT0()  asm volatile("cp.async.wait_group 0;"  ::: "memory")

__device__ __forceinline__ void split_bf16(float v, bf16& h, bf16& m) {
    h = __float2bfloat16(v);
    m = __float2bfloat16(v - __bfloat162float(h));
}

// 64B-row swizzle: 16B chunk index XORed with row bits [2:1] -> conflict-free LDSM
__device__ __forceinline__ uint32_t swz64(int r, int ch) {
    return (uint32_t)(r * 64 + (((unsigned)ch ^ (((unsigned)r >> 1) & 3u)) << 4));
}

// ---------------------------------------------------------------------------
// smem layout: 2 stages x 32KB. Each stage: Ah(8K) Am(8K) Bh(8K) Bm(8K).
// ---------------------------------------------------------------------------
#define STAGE_B   32768
#define OFF_AM    8192
#define OFF_BH    16384
#define OFF_BM    24576
#define SMEM_GEMM (2 * STAGE_B)   // 65536

__device__ __forceinline__ void load_stage(
    uint32_t sbuf,
    const bf16* __restrict__ Ah, const bf16* __restrict__ Am, int lda,
    const bf16* __restrict__ Bh, const bf16* __restrict__ Bm, int ldb,
    int kbase)
{
    const int tid = threadIdx.x;
    const int r  = tid >> 1;           // 0..127
    const int c0 = (tid & 1) * 2;      // chunks {0,1} or {2,3}
#pragma unroll
    for (int c = c0; c < c0 + 2; c++) {
        const uint32_t so = swz64(r, c);
        const size_t ga = (size_t)r * lda + kbase + c * 8;
        const size_t gb = (size_t)r * ldb + kbase + c * 8;
        cp16(sbuf + so,          Ah + ga);
        cp16(sbuf + OFF_AM + so, Am + ga);
        cp16(sbuf + OFF_BH + so, Bh + gb);
        cp16(sbuf + OFF_BM + so, Bm + gb);
    }
}

// C(128x128 fp32 regs) += 3xBF16-split A(128xK) . B(128xK)^T
// 8 warps, warp grid 4(m) x 2(n), warp tile 32x64.
__device__ __forceinline__ void gemm_mainloop(
    uint32_t sb,
    const bf16* __restrict__ Ah, const bf16* __restrict__ Am, int lda,
    const bf16* __restrict__ Bh, const bf16* __restrict__ Bm, int ldb,
    int chunks, float (&acc)[2][8][4])
{
#pragma unroll
    for (int a = 0; a < 2; a++)
#pragma unroll
        for (int b = 0; b < 8; b++)
#pragma unroll
            for (int cc = 0; cc < 4; cc++) acc[a][b][cc] = 0.f;

    const int tid = threadIdx.x, lane = tid & 31, wid = tid >> 5;
    const int wm = wid >> 1, wn = wid & 1;

    // ldmatrix lane->address mapping
    const int rA = wm * 32 + (lane & 15);                        // + mb*16
    const int hA = lane >> 4;                                    // k-half
    const int rB = wn * 64 + (lane & 7) + ((lane >> 4) & 1) * 8; // + nb*16
    const int hB = (lane >> 3) & 1;

    load_stage(sb, Ah, Am, lda, Bh, Bm, ldb, 0);
    CP_COMMIT();

    for (int c = 0; c < chunks; c++) {
        CP_WAIT0();
        __syncthreads();
        const uint32_t buf = sb + (c & 1) * STAGE_B;
        if (c + 1 < chunks) {
            load_stage(sb + ((c + 1) & 1) * STAGE_B, Ah, Am, lda, Bh, Bm, ldb,
                       (c + 1) * 32);
            CP_COMMIT();
        }
#pragma unroll
        for (int k16 = 0; k16 < 2; k16++) {
            uint32_t aH[2][4], aM[2][4];
#pragma unroll
            for (int mb = 0; mb < 2; mb++) {
                const uint32_t off = swz64(rA + mb * 16, k16 * 2 + hA);
                LDSM_X4(aH[mb], buf + off);
                LDSM_X4(aM[mb], buf + OFF_AM + off);
            }
#pragma unroll
            for (int nb = 0; nb < 4; nb++) {
                const uint32_t offB = swz64(rB + nb * 16, k16 * 2 + hB);
                uint32_t bH[4], bM[4];
                LDSM_X4(bH, buf + OFF_BH + offB);
                LDSM_X4(bM, buf + OFF_BM + offB);
#pragma unroll
                for (int mb = 0; mb < 2; mb++) {
                    mma_bf16(acc[mb][nb * 2 + 0], aH[mb], bH[0], bH[1]);
                    mma_bf16(acc[mb][nb * 2 + 1], aH[mb], bH[2], bH[3]);
                    mma_bf16(acc[mb][nb * 2 + 0], aH[mb], bM[0], bM[1]);
                    mma_bf16(acc[mb][nb * 2 + 1], aH[mb], bM[2], bM[3]);
                    mma_bf16(acc[mb][nb * 2 + 0], aM[mb], bH[0], bH[1]);
                    mma_bf16(acc[mb][nb * 2 + 1], aM[mb], bH[2], bH[3]);
                }
            }
        }
        __syncthreads();
    }
}

// Epilogue coordinates: acc[mb][j][reg]
//   row_local = wm*32 + mb*16 + (lane>>2) + (reg>=2)*8
//   col_local = wn*64 + j*8 + (lane&3)*2 + (reg&1)

// ---------------------------------------------------------------------------
// Kernel: fp32 -> (hi, mid) bf16 split conversion
// ---------------------------------------------------------------------------
__global__ void __launch_bounds__(256)
k_convert(const float* __restrict__ in, int sel, long n4) {
    bf16 *H, *M;
    if (sel == 0) { H = g_Hh; M = g_Hm; }
    else          { H = g_Wh4[sel - 1]; M = g_Wm4[sel - 1]; }
    long i = (long)blockIdx.x * blockDim.x + threadIdx.x;
    if (i >= n4) return;
    float4 v = ((const float4*)in)[i];
    alignas(8) bf16 h[4], m[4];
    split_bf16(v.x, h[0], m[0]);
    split_bf16(v.y, h[1], m[1]);
    split_bf16(v.z, h[2], m[2]);
    split_bf16(v.w, h[3], m[3]);
    *(uint2*)(H + i * 4) = *(const uint2*)h;
    *(uint2*)(M + i * 4) = *(const uint2*)m;
}

// ---------------------------------------------------------------------------
// Kernel: Q/K/V projection. grid (nt=16 [head], mt=64), block 256.
// ---------------------------------------------------------------------------
__global__ void __launch_bounds__(256)
k_proj(int which) {
    extern __shared__ char sm[];
    const uint32_t sb = smem_u32(sm);
    const int nt = blockIdx.x, mt = blockIdx.y;

    float acc[2][8][4];
    gemm_mainloop(sb,
        g_Hh + (size_t)mt * 128 * DM, g_Hm + (size_t)mt * 128 * DM, DM,
        g_Wh4[which] + (size_t)nt * 128 * DM, g_Wm4[which] + (size_t)nt * 128 * DM, DM,
        DM / 32, acc);

    bf16 *Gh, *Gm;
    if (which == 0)      { Gh = g_Qh; Gm = g_Qm; }
    else if (which == 1) { Gh = g_Kh; Gm = g_Km; }
    else                 { Gh = g_Vh; Gm = g_Vm; }

    const int tid = threadIdx.x, lane = tid & 31, wid = tid >> 5;
    const int wm = wid >> 1, wn = wid & 1;
#pragma unroll
    for (int mb = 0; mb < 2; mb++)
#pragma unroll
        for (int rp = 0; rp < 2; rp++) {
            const int m = mt * 128 + wm * 32 + mb * 16 + (lane >> 2) + rp * 8;
            const int b = m >> 11, s = m & (SEQ - 1);
            bf16* ph = Gh + ((size_t)(b * NH + nt) * SEQ + s) * DH;
            bf16* pm = Gm + ((size_t)(b * NH + nt) * SEQ + s) * DH;
#pragma unroll
            for (int j = 0; j < 8; j++) {
                const int col = wn * 64 + j * 8 + (lane & 3) * 2;
                bf16 h0, m0, h1, m1;
                split_bf16(acc[mb][j][rp * 2 + 0], h0, m0);
                split_bf16(acc[mb][j][rp * 2 + 1], h1, m1);
                *(__nv_bfloat162*)(ph + col) = __nv_bfloat162(h0, h1);
                *(__nv_bfloat162*)(pm + col) = __nv_bfloat162(m0, m1);
            }
        }
}

// ---------------------------------------------------------------------------
// Kernel: transpose V [bh,s,dh] -> [bh,dh,s] (both splits)
// ---------------------------------------------------------------------------
__global__ void __launch_bounds__(256)
k_transpose() {
    __shared__ bf16 tile[32][33];
    const int d0 = blockIdx.x * 32;
    const int s0 = blockIdx.y * 32;
    const int bh = blockIdx.z;
    const int tx = threadIdx.x, ty = threadIdx.y;
#pragma unroll
    for (int p = 0; p < 2; p++) {
        const bf16* src = p ? g_Vm : g_Vh;
        bf16* dst = p ? g_Vtm : g_Vth;
#pragma unroll
        for (int r = 0; r < 4; r++)
            tile[ty + r * 8][tx] =
                src[(size_t)bh * SEQ * DH + (size_t)(s0 + ty + r * 8) * DH + d0 + tx];
        __syncthreads();
#pragma unroll
        for (int r = 0; r < 4; r++)
            dst[(size_t)bh * DH * SEQ + (size_t)(d0 + ty + r * 8) * SEQ + s0 + tx] =
                tile[tx][ty + r * 8];
        __syncthreads();
    }
}

// ---------------------------------------------------------------------------
// Kernel: causal scores = Q . K^T (fp32 to g_S). grid (bj=16, bi=16, bh=64)
// ---------------------------------------------------------------------------
__global__ void __launch_bounds__(256)
k_scores() {
    const int bj = blockIdx.x, bi = blockIdx.y, bh = blockIdx.z;
    if (bj > bi) return;
    extern __shared__ char sm[];
    const uint32_t sb = smem_u32(sm);

    const size_t hb = (size_t)bh * SEQ * DH;
    float acc[2][8][4];
    gemm_mainloop(sb,
        g_Qh + hb + (size_t)bi * 128 * DH, g_Qm + hb + (size_t)bi * 128 * DH, DH,
        g_Kh + hb + (size_t)bj * 128 * DH, g_Km + hb + (size_t)bj * 128 * DH, DH,
        DH / 32, acc);

    const int tid = threadIdx.x, lane = tid & 31, wid = tid >> 5;
    const int wm = wid >> 1, wn = wid & 1;
    float* Sp = g_S + (size_t)bh * SEQ * SEQ;
#pragma unroll
    for (int mb = 0; mb < 2; mb++)
#pragma unroll
        for (int rp = 0; rp < 2; rp++) {
            const int m = bi * 128 + wm * 32 + mb * 16 + (lane >> 2) + rp * 8;
            float* dst = Sp + (size_t)m * SEQ + bj * 128;
#pragma unroll
            for (int j = 0; j < 8; j++) {
                const int col = wn * 64 + j * 8 + (lane & 3) * 2;
                *(float2*)(dst + col) =
                    make_float2(acc[mb][j][rp * 2], acc[mb][j][rp * 2 + 1]);
            }
        }
}

// ---------------------------------------------------------------------------
// Kernel: row softmax. Reads its fp32 row from g_S into registers, then
// overwrites the SAME 8KB row region in place with bf16 splits:
//   h at bf16 offsets [0, SEQ), m at [SEQ, 2*SEQ).
// Also writes fp32 probs to Pext when attn_weights live in d_out.
// ---------------------------------------------------------------------------
__device__ __forceinline__ float warp_max(float v) {
#pragma unroll
    for (int o = 16; o > 0; o >>= 1) v = fmaxf(v, __shfl_xor_sync(0xffffffffu, v, o));
    return v;
}
__device__ __forceinline__ float warp_sum(float v) {
#pragma unroll
    for (int o = 16; o > 0; o >>= 1) v += __shfl_xor_sync(0xffffffffu, v, o);
    return v;
}

__global__ void __launch_bounds__(256)
k_softmax(float* __restrict__ Pext, int use_ext) {
    __shared__ float shm[8];
    __shared__ float shs[8];

    const size_t row = blockIdx.x;
    const int q = (int)(row & (SEQ - 1));
    const float* pr = g_S + row * (size_t)SEQ;
    const int tid = threadIdx.x;
    const int wid = tid >> 5, lid = tid & 31;

    float v[8];
    float m = -CUDART_INF_F;
#pragma unroll
    for (int k = 0; k < 8; k++) {
        const int j = tid + k * 256;
        v[k] = (j <= q) ? pr[j] : -CUDART_INF_F;
        m = fmaxf(m, v[k]);
    }
    m = warp_max(m);
    if (lid == 0) shm[wid] = m;
    __syncthreads();          // also guarantees all row reads complete before writes
    if (tid < 32) {
        float t = (tid < 8) ? shm[tid] : -CUDART_INF_F;
        t = warp_max(t);
        if (tid == 0) shm[0] = t;
    }
    __syncthreads();
    m = shm[0];

    float s = 0.f;
#pragma unroll
    for (int k = 0; k < 8; k++) {
        const float e = expf(v[k] - m);
        v[k] = e;
        s += e;
    }
    s = warp_sum(s);
    if (lid == 0) shs[wid] = s;
    __syncthreads();
    if (tid < 32) {
        float t = (tid < 8) ? shs[tid] : 0.f;
        t = warp_sum(t);
        if (tid == 0) shs[0] = t;
    }
    __syncthreads();
    const float inv = 1.f / shs[0];

    const int jmax = ((q >> 7) + 1) << 7;    // diagonal-tile end (same for whole q-tile)
    bf16* ph = (bf16*)(g_S) + row * (size_t)(2 * SEQ);        // in-place: first 4KB
    bf16* pm = ph + SEQ;                                       // second 4KB
#pragma unroll
    for (int k = 0; k < 8; k++) {
        const int j = tid + k * 256;
        const float p = v[k] * inv;
        if (use_ext) Pext[row * (size_t)SEQ + j] = p;
        if (j < jmax) {
            bf16 h, md;
            split_bf16(p, h, md);
            ph[j] = h; pm[j] = md;
        }
    }
}

// ---------------------------------------------------------------------------
// Kernel: AV = P . V (causal-truncated). grid (bi=16, bh=64)
// P splits live in-place inside g_S: row stride 2*SEQ bf16, m at +SEQ.
// ---------------------------------------------------------------------------
__global__ void __launch_bounds__(256)
k_av() {
    const int bi = blockIdx.x, bh = blockIdx.y;
    extern __shared__ char sm[];
    const uint32_t sb = smem_u32(sm);

    const bf16* Pbase = (const bf16*)(g_S) +
                        (size_t)(bh * SEQ + bi * 128) * (size_t)(2 * SEQ);

    float acc[2][8][4];
    gemm_mainloop(sb,
        Pbase, Pbase + SEQ, 2 * SEQ,
        g_Vth + (size_t)bh * DH * SEQ,
        g_Vtm + (size_t)bh * DH * SEQ, SEQ,
        (bi + 1) * 4, acc);

    const int tid = threadIdx.x, lane = tid & 31, wid = tid >> 5;
    const int wm = wid >> 1, wn = wid & 1;
    const int b = bh >> 4, h = bh & 15;
#pragma unroll
    for (int mb = 0; mb < 2; mb++)
#pragma unroll
        for (int rp = 0; rp < 2; rp++) {
            const int s = bi * 128 + wm * 32 + mb * 16 + (lane >> 2) + rp * 8;
            bf16* ph = g_AOh + ((size_t)(b * SEQ + s)) * DM + h * 128;
            bf16* pm = g_AOm + ((size_t)(b * SEQ + s)) * DM + h * 128;
#pragma unroll
            for (int j = 0; j < 8; j++) {
                const int col = wn * 64 + j * 8 + (lane & 3) * 2;
                bf16 h0, m0, h1, m1;
                split_bf16(acc[mb][j][rp * 2 + 0], h0, m0);
                split_bf16(acc[mb][j][rp * 2 + 1], h1, m1);
                *(__nv_bfloat162*)(ph + col) = __nv_bfloat162(h0, h1);
                *(__nv_bfloat162*)(pm + col) = __nv_bfloat162(m0, m1);
            }
        }
}

// ---------------------------------------------------------------------------
// Kernel: out = AO . Wo^T + bo (fp32 to d_out). grid (nt=16, mt=64)
// ---------------------------------------------------------------------------
__global__ void __launch_bounds__(256)
k_out(const float* __restrict__ bias, float* __restrict__ Out) {
    extern __shared__ char sm[];
    const uint32_t sb = smem_u32(sm);
    const int nt = blockIdx.x, mt = blockIdx.y;

    float acc[2][8][4];
    gemm_mainloop(sb,
        g_AOh + (size_t)mt * 128 * DM, g_AOm + (size_t)mt * 128 * DM, DM,
        g_Wh4[3] + (size_t)nt * 128 * DM, g_Wm4[3] + (size_t)nt * 128 * DM, DM,
        DM / 32, acc);

    const int tid = threadIdx.x, lane = tid & 31, wid = tid >> 5;
    const int wm = wid >> 1, wn = wid & 1;
#pragma unroll
    for (int mb = 0; mb < 2; mb++)
#pragma unroll
        for (int rp = 0; rp < 2; rp++) {
            const int m = mt * 128 + wm * 32 + mb * 16 + (lane >> 2) + rp * 8;
            float* dst = Out + (size_t)m * DM + nt * 128;
#pragma unroll
            for (int j = 0; j < 8; j++) {
                const int col = wn * 64 + j * 8 + (lane & 3) * 2;
                *(float2*)(dst + col) =
                    make_float2(acc[mb][j][rp * 2] + bias[nt * 128 + col],
                                acc[mb][j][rp * 2 + 1] + bias[nt * 128 + col + 1]);
            }
        }
}

// ---------------------------------------------------------------------------
// Launch
// ---------------------------------------------------------------------------
extern "C" void kernel_launch(void* const* d_in, const int* in_sizes, int n_in,
                              void* d_out, int out_size) {
    const float* hs = (const float*)d_in[0];
    const float* wq = (const float*)d_in[1];
    const float* wk = (const float*)d_in[2];
    const float* wv = (const float*)d_in[3];
    const float* wo = (const float*)d_in[4];
    const float* bo = (const float*)d_in[5];
    float* out = (float*)d_out;

    const long long OUT_ELEMS = (long long)MROWS * DM;       // 16,777,216
    const long long WEI_ELEMS = (long long)BH * SEQ * SEQ;   // 268,435,456
    const int use_ext = ((long long)out_size >= OUT_ELEMS + WEI_ELEMS) ? 1 : 0;
    float* Pext = use_ext ? (out + OUT_ELEMS) : nullptr;

    cudaFuncSetAttribute(k_proj,   cudaFuncAttributeMaxDynamicSharedMemorySize, SMEM_GEMM);
    cudaFuncSetAttribute(k_scores, cudaFuncAttributeMaxDynamicSharedMemorySize, SMEM_GEMM);
    cudaFuncSetAttribute(k_av,     cudaFuncAttributeMaxDynamicSharedMemorySize, SMEM_GEMM);
    cudaFuncSetAttribute(k_out,    cudaFuncAttributeMaxDynamicSharedMemorySize, SMEM_GEMM);

    const long nH4 = (long)MROWS * DM / 4;
    const long nW4 = (long)DM * DM / 4;
    k_convert<<<(unsigned)((nH4 + 255) / 256), 256>>>(hs, 0, nH4);
    k_convert<<<(unsigned)((nW4 + 255) / 256), 256>>>(wq, 1, nW4);
    k_convert<<<(unsigned)((nW4 + 255) / 256), 256>>>(wk, 2, nW4);
    k_convert<<<(unsigned)((nW4 + 255) / 256), 256>>>(wv, 3, nW4);
    k_convert<<<(unsigned)((nW4 + 255) / 256), 256>>>(wo, 4, nW4);

    k_proj<<<dim3(16, 64), 256, SMEM_GEMM>>>(0);
    k_proj<<<dim3(16, 64), 256, SMEM_GEMM>>>(1);
    k_proj<<<dim3(16, 64), 256, SMEM_GEMM>>>(2);

    k_transpose<<<dim3(4, 64, BH), dim3(32, 8)>>>();

    k_scores<<<dim3(16, 16, BH), 256, SMEM_GEMM>>>();
    k_softmax<<<BH * SEQ, 256>>>(Pext, use_ext);
    k_av<<<dim3(16, BH), 256, SMEM_GEMM>>>();
    k_out<<<dim3(16, 64), 256, SMEM_GEMM>>>(bo, out);
}

// round 6
// speedup vs baseline: 2.5553x; 1.0363x over previous
#include <cuda_runtime.h>
#include <cuda_bf16.h>
#include <math_constants.h>
#include <cstdint>
#include <cstddef>

#define BATCH 4
#define NH    16
#define SEQ   2048
#define DH    128
#define DM    2048
#define BH    (BATCH*NH)     // 64
#define MROWS (BATCH*SEQ)    // 8192

typedef __nv_bfloat16 bf16;

// ---------------------------------------------------------------------------
// Device scratch (static globals; total ~1.66 GB, must stay < 2 GB for x86 link)
// ---------------------------------------------------------------------------
__device__ bf16 g_Hh[(size_t)MROWS * DM];
__device__ bf16 g_Hm[(size_t)MROWS * DM];
__device__ bf16 g_Wh4[4][(size_t)DM * DM];
__device__ bf16 g_Wm4[4][(size_t)DM * DM];
__device__ bf16 g_Qh[(size_t)BH * SEQ * DH];
__device__ bf16 g_Qm[(size_t)BH * SEQ * DH];
__device__ bf16 g_Kh[(size_t)BH * SEQ * DH];
__device__ bf16 g_Km[(size_t)BH * SEQ * DH];
__device__ bf16 g_Vh[(size_t)BH * SEQ * DH];
__device__ bf16 g_Vm[(size_t)BH * SEQ * DH];
__device__ bf16 g_Vth[(size_t)BH * DH * SEQ];
__device__ bf16 g_Vtm[(size_t)BH * DH * SEQ];
// g_S: 1 GiB. fp32 scores; softmax overwrites each 8KB row IN PLACE with
// bf16 splits: h at bf16 offsets [0,2048), m at [2048,4096).
__device__ float g_S[(size_t)BH * SEQ * SEQ];
__device__ bf16 g_AOh[(size_t)MROWS * DM];
__device__ bf16 g_AOm[(size_t)MROWS * DM];

// ---------------------------------------------------------------------------
// PTX helpers (sm_80-era: mma.sync / ldmatrix / cp.async — valid on sm_100)
// ---------------------------------------------------------------------------
__device__ __forceinline__ uint32_t smem_u32(const void* p) {
    uint32_t a;
    asm("{ .reg .u64 t; cvta.to.shared.u64 t, %1; cvt.u32.u64 %0, t; }"
        : "=r"(a) : "l"(p));
    return a;
}

#define LDSM_X4(R, addr) \
    asm volatile("ldmatrix.sync.aligned.m8n8.x4.shared.b16 {%0,%1,%2,%3}, [%4];" \
                 : "=r"((R)[0]), "=r"((R)[1]), "=r"((R)[2]), "=r"((R)[3]) : "r"(addr))

__device__ __forceinline__ void mma_bf16(float* c, const uint32_t* a,
                                         uint32_t b0, uint32_t b1) {
    asm volatile(
        "mma.sync.aligned.m16n8k16.row.col.f32.bf16.bf16.f32 "
        "{%0,%1,%2,%3}, {%4,%5,%6,%7}, {%8,%9}, {%0,%1,%2,%3};"
        : "+f"(c[0]), "+f"(c[1]), "+f"(c[2]), "+f"(c[3])
        : "r"(a[0]), "r"(a[1]), "r"(a[2]), "r"(a[3]), "r"(b0), "r"(b1));
}

__device__ __forceinline__ void cp16(uint32_t s, const void* g) {
    asm volatile("cp.async.cg.shared.global [%0], [%1], 16;" :: "r"(s), "l"(g));
}
#define CP_COMMIT() asm volatile("cp.async.commit_group;" ::: "memory")
#define CP_WAIT1()  asm volatile("cp.async.wait_group 1;"  ::: "memory")
#define CP_WAIT0()  asm volatile("cp.async.wait_group 0;"  ::: "memory")

__device__ __forceinline__ void split_bf16(float v, bf16& h, bf16& m) {
    h = __float2bfloat16(v);
    m = __float2bfloat16(v - __bfloat162float(h));
}

// 64B-row swizzle: 16B chunk index XORed with row bits [2:1] -> conflict-free LDSM
__device__ __forceinline__ uint32_t swz64(int r, int ch) {
    return (uint32_t)(r * 64 + (((unsigned)ch ^ (((unsigned)r >> 1) & 3u)) << 4));
}

// ---------------------------------------------------------------------------
// smem layout: 3 stages x 32KB. Each stage: Ah(8K) Am(8K) Bh(8K) Bm(8K).
// ---------------------------------------------------------------------------
#define STAGE_B   32768
#define OFF_AM    8192
#define OFF_BH    16384
#define OFF_BM    24576
#define SMEM_GEMM (3 * STAGE_B)   // 98304; 2 CTAs/SM -> 192KB < 228KB

__device__ __forceinline__ void load_stage(
    uint32_t sbuf,
    const bf16* __restrict__ Ah, const bf16* __restrict__ Am, int lda,
    const bf16* __restrict__ Bh, const bf16* __restrict__ Bm, int ldb,
    int kbase)
{
    const int tid = threadIdx.x;
    const int r  = tid >> 1;           // 0..127
    const int c0 = (tid & 1) * 2;      // chunks {0,1} or {2,3}
#pragma unroll
    for (int c = c0; c < c0 + 2; c++) {
        const uint32_t so = swz64(r, c);
        const size_t ga = (size_t)r * lda + kbase + c * 8;
        const size_t gb = (size_t)r * ldb + kbase + c * 8;
        cp16(sbuf + so,          Ah + ga);
        cp16(sbuf + OFF_AM + so, Am + ga);
        cp16(sbuf + OFF_BH + so, Bh + gb);
        cp16(sbuf + OFF_BM + so, Bm + gb);
    }
}

// C(128x128 fp32 regs) += 3xBF16-split A(128xK) . B(128xK)^T
// 8 warps, warp grid 4(m) x 2(n), warp tile 32x64. 3-stage cp.async ring.
// chunks >= 2 always (min case: DH/32 = 4).
__device__ __forceinline__ void gemm_mainloop(
    uint32_t sb,
    const bf16* __restrict__ Ah, const bf16* __restrict__ Am, int lda,
    const bf16* __restrict__ Bh, const bf16* __restrict__ Bm, int ldb,
    int chunks, float (&acc)[2][8][4])
{
#pragma unroll
    for (int a = 0; a < 2; a++)
#pragma unroll
        for (int b = 0; b < 8; b++)
#pragma unroll
            for (int cc = 0; cc < 4; cc++) acc[a][b][cc] = 0.f;

    const int tid = threadIdx.x, lane = tid & 31, wid = tid >> 5;
    const int wm = wid >> 1, wn = wid & 1;

    // ldmatrix lane->address mapping
    const int rA = wm * 32 + (lane & 15);                        // + mb*16
    const int hA = lane >> 4;                                    // k-half
    const int rB = wn * 64 + (lane & 7) + ((lane >> 4) & 1) * 8; // + nb*16
    const int hB = (lane >> 3) & 1;

    load_stage(sb,           Ah, Am, lda, Bh, Bm, ldb, 0);
    CP_COMMIT();
    load_stage(sb + STAGE_B, Ah, Am, lda, Bh, Bm, ldb, 32);
    CP_COMMIT();

    int stage = 0;         // stage index of chunk c
    int pstage = 2;        // stage index of chunk c+2
    for (int c = 0; c < chunks; c++) {
        if (c + 1 < chunks) CP_WAIT1(); else CP_WAIT0();
        __syncthreads();   // all warps: data visible AND done computing stage pstage
        if (c + 2 < chunks) {
            load_stage(sb + pstage * STAGE_B, Ah, Am, lda, Bh, Bm, ldb,
                       (c + 2) * 32);
            CP_COMMIT();
        }
        const uint32_t buf = sb + stage * STAGE_B;
#pragma unroll
        for (int k16 = 0; k16 < 2; k16++) {
            uint32_t aH[2][4], aM[2][4];
#pragma unroll
            for (int mb = 0; mb < 2; mb++) {
                const uint32_t off = swz64(rA + mb * 16, k16 * 2 + hA);
                LDSM_X4(aH[mb], buf + off);
                LDSM_X4(aM[mb], buf + OFF_AM + off);
            }
#pragma unroll
            for (int nb = 0; nb < 4; nb++) {
                const uint32_t offB = swz64(rB + nb * 16, k16 * 2 + hB);
                uint32_t bH[4], bM[4];
                LDSM_X4(bH, buf + OFF_BH + offB);
                LDSM_X4(bM, buf + OFF_BM + offB);
#pragma unroll
                for (int mb = 0; mb < 2; mb++) {
                    mma_bf16(acc[mb][nb * 2 + 0], aH[mb], bH[0], bH[1]);
                    mma_bf16(acc[mb][nb * 2 + 1], aH[mb], bH[2], bH[3]);
                    mma_bf16(acc[mb][nb * 2 + 0], aH[mb], bM[0], bM[1]);
                    mma_bf16(acc[mb][nb * 2 + 1], aH[mb], bM[2], bM[3]);
                    mma_bf16(acc[mb][nb * 2 + 0], aM[mb], bH[0], bH[1]);
                    mma_bf16(acc[mb][nb * 2 + 1], aM[mb], bH[2], bH[3]);
                }
            }
        }
        stage = (stage == 2) ? 0 : stage + 1;
        pstage = (pstage == 2) ? 0 : pstage + 1;
    }
    __syncthreads();
}

// Epilogue coordinates: acc[mb][j][reg]
//   row_local = wm*32 + mb*16 + (lane>>2) + (reg>=2)*8
//   col_local = wn*64 + j*8 + (lane&3)*2 + (reg&1)

// ---------------------------------------------------------------------------
// Kernel: fp32 -> (hi, mid) bf16 split conversion
// ---------------------------------------------------------------------------
__global__ void __launch_bounds__(256)
k_convert(const float* __restrict__ in, int sel, long n4) {
    bf16 *H, *M;
    if (sel == 0) { H = g_Hh; M = g_Hm; }
    else          { H = g_Wh4[sel - 1]; M = g_Wm4[sel - 1]; }
    long i = (long)blockIdx.x * blockDim.x + threadIdx.x;
    if (i >= n4) return;
    float4 v = ((const float4*)in)[i];
    alignas(8) bf16 h[4], m[4];
    split_bf16(v.x, h[0], m[0]);
    split_bf16(v.y, h[1], m[1]);
    split_bf16(v.z, h[2], m[2]);
    split_bf16(v.w, h[3], m[3]);
    *(uint2*)(H + i * 4) = *(const uint2*)h;
    *(uint2*)(M + i * 4) = *(const uint2*)m;
}

// ---------------------------------------------------------------------------
// Kernel: Q/K/V projection, all three in one launch.
// grid (nt=16 [head], mt=64, which=3), block 256.
// ---------------------------------------------------------------------------
__global__ void __launch_bounds__(256, 2)
k_proj(void) {
    extern __shared__ char sm[];
    const uint32_t sb = smem_u32(sm);
    const int nt = blockIdx.x, mt = blockIdx.y, which = blockIdx.z;

    float acc[2][8][4];
    gemm_mainloop(sb,
        g_Hh + (size_t)mt * 128 * DM, g_Hm + (size_t)mt * 128 * DM, DM,
        g_Wh4[which] + (size_t)nt * 128 * DM, g_Wm4[which] + (size_t)nt * 128 * DM, DM,
        DM / 32, acc);

    bf16 *Gh, *Gm;
    if (which == 0)      { Gh = g_Qh; Gm = g_Qm; }
    else if (which == 1) { Gh = g_Kh; Gm = g_Km; }
    else                 { Gh = g_Vh; Gm = g_Vm; }

    const int tid = threadIdx.x, lane = tid & 31, wid = tid >> 5;
    const int wm = wid >> 1, wn = wid & 1;
#pragma unroll
    for (int mb = 0; mb < 2; mb++)
#pragma unroll
        for (int rp = 0; rp < 2; rp++) {
            const int m = mt * 128 + wm * 32 + mb * 16 + (lane >> 2) + rp * 8;
            const int b = m >> 11, s = m & (SEQ - 1);
            bf16* ph = Gh + ((size_t)(b * NH + nt) * SEQ + s) * DH;
            bf16* pm = Gm + ((size_t)(b * NH + nt) * SEQ + s) * DH;
#pragma unroll
            for (int j = 0; j < 8; j++) {
                const int col = wn * 64 + j * 8 + (lane & 3) * 2;
                bf16 h0, m0, h1, m1;
                split_bf16(acc[mb][j][rp * 2 + 0], h0, m0);
                split_bf16(acc[mb][j][rp * 2 + 1], h1, m1);
                *(__nv_bfloat162*)(ph + col) = __nv_bfloat162(h0, h1);
                *(__nv_bfloat162*)(pm + col) = __nv_bfloat162(m0, m1);
            }
        }
}

// ---------------------------------------------------------------------------
// Kernel: transpose V [bh,s,dh] -> [bh,dh,s] (both splits)
// ---------------------------------------------------------------------------
__global__ void __launch_bounds__(256)
k_transpose() {
    __shared__ bf16 tile[32][33];
    const int d0 = blockIdx.x * 32;
    const int s0 = blockIdx.y * 32;
    const int bh = blockIdx.z;
    const int tx = threadIdx.x, ty = threadIdx.y;
#pragma unroll
    for (int p = 0; p < 2; p++) {
        const bf16* src = p ? g_Vm : g_Vh;
        bf16* dst = p ? g_Vtm : g_Vth;
#pragma unroll
        for (int r = 0; r < 4; r++)
            tile[ty + r * 8][tx] =
                src[(size_t)bh * SEQ * DH + (size_t)(s0 + ty + r * 8) * DH + d0 + tx];
        __syncthreads();
#pragma unroll
        for (int r = 0; r < 4; r++)
            dst[(size_t)bh * DH * SEQ + (size_t)(d0 + ty + r * 8) * SEQ + s0 + tx] =
                tile[tx][ty + r * 8];
        __syncthreads();
    }
}

// ---------------------------------------------------------------------------
// Kernel: causal scores = Q . K^T (fp32 to g_S). grid (bj=16, bi=16, bh=64)
// ---------------------------------------------------------------------------
__global__ void __launch_bounds__(256, 2)
k_scores() {
    const int bj = blockIdx.x, bi = blockIdx.y, bh = blockIdx.z;
    if (bj > bi) return;
    extern __shared__ char sm[];
    const uint32_t sb = smem_u32(sm);

    const size_t hb = (size_t)bh * SEQ * DH;
    float acc[2][8][4];
    gemm_mainloop(sb,
        g_Qh + hb + (size_t)bi * 128 * DH, g_Qm + hb + (size_t)bi * 128 * DH, DH,
        g_Kh + hb + (size_t)bj * 128 * DH, g_Km + hb + (size_t)bj * 128 * DH, DH,
        DH / 32, acc);

    const int tid = threadIdx.x, lane = tid & 31, wid = tid >> 5;
    const int wm = wid >> 1, wn = wid & 1;
    float* Sp = g_S + (size_t)bh * SEQ * SEQ;
#pragma unroll
    for (int mb = 0; mb < 2; mb++)
#pragma unroll
        for (int rp = 0; rp < 2; rp++) {
            const int m = bi * 128 + wm * 32 + mb * 16 + (lane >> 2) + rp * 8;
            float* dst = Sp + (size_t)m * SEQ + bj * 128;
#pragma unroll
            for (int j = 0; j < 8; j++) {
                const int col = wn * 64 + j * 8 + (lane & 3) * 2;
                *(float2*)(dst + col) =
                    make_float2(acc[mb][j][rp * 2], acc[mb][j][rp * 2 + 1]);
            }
        }
}

// ---------------------------------------------------------------------------
// Kernel: row softmax; in-place bf16 splits into g_S row; fp32 to Pext if
// attn_weights live in d_out.
// ---------------------------------------------------------------------------
__device__ __forceinline__ float warp_max(float v) {
#pragma unroll
    for (int o = 16; o > 0; o >>= 1) v = fmaxf(v, __shfl_xor_sync(0xffffffffu, v, o));
    return v;
}
__device__ __forceinline__ float warp_sum(float v) {
#pragma unroll
    for (int o = 16; o > 0; o >>= 1) v += __shfl_xor_sync(0xffffffffu, v, o);
    return v;
}

__global__ void __launch_bounds__(256)
k_softmax(float* __restrict__ Pext, int use_ext) {
    __shared__ float shm[8];
    __shared__ float shs[8];

    const size_t row = blockIdx.x;
    const int q = (int)(row & (SEQ - 1));
    const float* pr = g_S + row * (size_t)SEQ;
    const int tid = threadIdx.x;
    const int wid = tid >> 5, lid = tid & 31;

    float v[8];
    float m = -CUDART_INF_F;
#pragma unroll
    for (int k = 0; k < 8; k++) {
        const int j = tid + k * 256;
        v[k] = (j <= q) ? pr[j] : -CUDART_INF_F;
        m = fmaxf(m, v[k]);
    }
    m = warp_max(m);
    if (lid == 0) shm[wid] = m;
    __syncthreads();          // guarantees all row reads complete before in-place writes
    if (tid < 32) {
        float t = (tid < 8) ? shm[tid] : -CUDART_INF_F;
        t = warp_max(t);
        if (tid == 0) shm[0] = t;
    }
    __syncthreads();
    m = shm[0];

    float s = 0.f;
#pragma unroll
    for (int k = 0; k < 8; k++) {
        const float e = expf(v[k] - m);
        v[k] = e;
        s += e;
    }
    s = warp_sum(s);
    if (lid == 0) shs[wid] = s;
    __syncthreads();
    if (tid < 32) {
        float t = (tid < 8) ? shs[tid] : 0.f;
        t = warp_sum(t);
        if (tid == 0) shs[0] = t;
    }
    __syncthreads();
    const float inv = 1.f / shs[0];

    const int jmax = ((q >> 7) + 1) << 7;    // diagonal-tile end (same for whole q-tile)
    bf16* ph = (bf16*)(g_S) + row * (size_t)(2 * SEQ);
    bf16* pm = ph + SEQ;
#pragma unroll
    for (int k = 0; k < 8; k++) {
        const int j = tid + k * 256;
        const float p = v[k] * inv;
        if (use_ext) Pext[row * (size_t)SEQ + j] = p;
        if (j < jmax) {
            bf16 h, md;
            split_bf16(p, h, md);
            ph[j] = h; pm[j] = md;
        }
    }
}

// ---------------------------------------------------------------------------
// Kernel: AV = P . V (causal-truncated). grid (bi=16, bh=64)
// P splits live in-place inside g_S: row stride 2*SEQ bf16, m at +SEQ.
// ---------------------------------------------------------------------------
__global__ void __launch_bounds__(256, 2)
k_av() {
    const int bi = blockIdx.x, bh = blockIdx.y;
    extern __shared__ char sm[];
    const uint32_t sb = smem_u32(sm);

    const bf16* Pbase = (const bf16*)(g_S) +
                        (size_t)(bh * SEQ + bi * 128) * (size_t)(2 * SEQ);

    float acc[2][8][4];
    gemm_mainloop(sb,
        Pbase, Pbase + SEQ, 2 * SEQ,
        g_Vth + (size_t)bh * DH * SEQ,
        g_Vtm + (size_t)bh * DH * SEQ, SEQ,
        (bi + 1) * 4, acc);

    const int tid = threadIdx.x, lane = tid & 31, wid = tid >> 5;
    const int wm = wid >> 1, wn = wid & 1;
    const int b = bh >> 4, h = bh & 15;
#pragma unroll
    for (int mb = 0; mb < 2; mb++)
#pragma unroll
        for (int rp = 0; rp < 2; rp++) {
            const int s = bi * 128 + wm * 32 + mb * 16 + (lane >> 2) + rp * 8;
            bf16* ph = g_AOh + ((size_t)(b * SEQ + s)) * DM + h * 128;
            bf16* pm = g_AOm + ((size_t)(b * SEQ + s)) * DM + h * 128;
#pragma unroll
            for (int j = 0; j < 8; j++) {
                const int col = wn * 64 + j * 8 + (lane & 3) * 2;
                bf16 h0, m0, h1, m1;
                split_bf16(acc[mb][j][rp * 2 + 0], h0, m0);
                split_bf16(acc[mb][j][rp * 2 + 1], h1, m1);
                *(__nv_bfloat162*)(ph + col) = __nv_bfloat162(h0, h1);
                *(__nv_bfloat162*)(pm + col) = __nv_bfloat162(m0, m1);
            }
        }
}

// ---------------------------------------------------------------------------
// Kernel: out = AO . Wo^T + bo (fp32 to d_out). grid (nt=16, mt=64)
// ---------------------------------------------------------------------------
__global__ void __launch_bounds__(256, 2)
k_out(const float* __restrict__ bias, float* __restrict__ Out) {
    extern __shared__ char sm[];
    const uint32_t sb = smem_u32(sm);
    const int nt = blockIdx.x, mt = blockIdx.y;

    float acc[2][8][4];
    gemm_mainloop(sb,
        g_AOh + (size_t)mt * 128 * DM, g_AOm + (size_t)mt * 128 * DM, DM,
        g_Wh4[3] + (size_t)nt * 128 * DM, g_Wm4[3] + (size_t)nt * 128 * DM, DM,
        DM / 32, acc);

    const int tid = threadIdx.x, lane = tid & 31, wid = tid >> 5;
    const int wm = wid >> 1, wn = wid & 1;
#pragma unroll
    for (int mb = 0; mb < 2; mb++)
#pragma unroll
        for (int rp = 0; rp < 2; rp++) {
            const int m = mt * 128 + wm * 32 + mb * 16 + (lane >> 2) + rp * 8;
            float* dst = Out + (size_t)m * DM + nt * 128;
#pragma unroll
            for (int j = 0; j < 8; j++) {
                const int col = wn * 64 + j * 8 + (lane & 3) * 2;
                *(float2*)(dst + col) =
                    make_float2(acc[mb][j][rp * 2] + bias[nt * 128 + col],
                                acc[mb][j][rp * 2 + 1] + bias[nt * 128 + col + 1]);
            }
        }
}

// ---------------------------------------------------------------------------
// Launch
// ---------------------------------------------------------------------------
extern "C" void kernel_launch(void* const* d_in, const int* in_sizes, int n_in,
                              void* d_out, int out_size) {
    const float* hs = (const float*)d_in[0];
    const float* wq = (const float*)d_in[1];
    const float* wk = (const float*)d_in[2];
    const float* wv = (const float*)d_in[3];
    const float* wo = (const float*)d_in[4];
    const float* bo = (const float*)d_in[5];
    float* out = (float*)d_out;

    const long long OUT_ELEMS = (long long)MROWS * DM;       // 16,777,216
    const long long WEI_ELEMS = (long long)BH * SEQ * SEQ;   // 268,435,456
    const int use_ext = ((long long)out_size >= OUT_ELEMS + WEI_ELEMS) ? 1 : 0;
    float* Pext = use_ext ? (out + OUT_ELEMS) : nullptr;

    cudaFuncSetAttribute(k_proj,   cudaFuncAttributeMaxDynamicSharedMemorySize, SMEM_GEMM);
    cudaFuncSetAttribute(k_scores, cudaFuncAttributeMaxDynamicSharedMemorySize, SMEM_GEMM);
    cudaFuncSetAttribute(k_av,     cudaFuncAttributeMaxDynamicSharedMemorySize, SMEM_GEMM);
    cudaFuncSetAttribute(k_out,    cudaFuncAttributeMaxDynamicSharedMemorySize, SMEM_GEMM);

    const long nH4 = (long)MROWS * DM / 4;
    const long nW4 = (long)DM * DM / 4;
    k_convert<<<(unsigned)((nH4 + 255) / 256), 256>>>(hs, 0, nH4);
    k_convert<<<(unsigned)((nW4 + 255) / 256), 256>>>(wq, 1, nW4);
    k_convert<<<(unsigned)((nW4 + 255) / 256), 256>>>(wk, 2, nW4);
    k_convert<<<(unsigned)((nW4 + 255) / 256), 256>>>(wv, 3, nW4);
    k_convert<<<(unsigned)((nW4 + 255) / 256), 256>>>(wo, 4, nW4);

    k_proj<<<dim3(16, 64, 3), 256, SMEM_GEMM>>>();

    k_transpose<<<dim3(4, 64, BH), dim3(32, 8)>>>();

    k_scores<<<dim3(16, 16, BH), 256, SMEM_GEMM>>>();
    k_softmax<<<BH * SEQ, 256>>>(Pext, use_ext);
    k_av<<<dim3(16, BH), 256, SMEM_GEMM>>>();
    k_out<<<dim3(16, 64), 256, SMEM_GEMM>>>(bo, out);
}

// round 7
// speedup vs baseline: 2.5879x; 1.0128x over previous
#include <cuda_runtime.h>
#include <cuda_bf16.h>
#include <math_constants.h>
#include <cstdint>
#include <cstddef>

#define BATCH 4
#define NH    16
#define SEQ   2048
#define DH    128
#define DM    2048
#define BH    (BATCH*NH)     // 64
#define MROWS (BATCH*SEQ)    // 8192

typedef __nv_bfloat16 bf16;

// ---------------------------------------------------------------------------
// Device scratch (static globals; total ~1.66 GB, must stay < 2 GB for x86 link)
// ---------------------------------------------------------------------------
__device__ bf16 g_Hh[(size_t)MROWS * DM];
__device__ bf16 g_Hm[(size_t)MROWS * DM];
__device__ bf16 g_Wh4[4][(size_t)DM * DM];
__device__ bf16 g_Wm4[4][(size_t)DM * DM];
__device__ bf16 g_Qh[(size_t)BH * SEQ * DH];
__device__ bf16 g_Qm[(size_t)BH * SEQ * DH];
__device__ bf16 g_Kh[(size_t)BH * SEQ * DH];
__device__ bf16 g_Km[(size_t)BH * SEQ * DH];
__device__ bf16 g_Vh[(size_t)BH * SEQ * DH];
__device__ bf16 g_Vm[(size_t)BH * SEQ * DH];
__device__ bf16 g_Vth[(size_t)BH * DH * SEQ];
__device__ bf16 g_Vtm[(size_t)BH * DH * SEQ];
// g_S: 1 GiB. fp32 scores; softmax overwrites each 8KB row IN PLACE with
// bf16 splits: h at bf16 offsets [0,2048), m at [2048,4096).
__device__ float g_S[(size_t)BH * SEQ * SEQ];
__device__ bf16 g_AOh[(size_t)MROWS * DM];
__device__ bf16 g_AOm[(size_t)MROWS * DM];

// ---------------------------------------------------------------------------
// PTX helpers (sm_80-era: mma.sync / ldmatrix / cp.async — valid on sm_100)
// ---------------------------------------------------------------------------
__device__ __forceinline__ uint32_t smem_u32(const void* p) {
    uint32_t a;
    asm("{ .reg .u64 t; cvta.to.shared.u64 t, %1; cvt.u32.u64 %0, t; }"
        : "=r"(a) : "l"(p));
    return a;
}

#define LDSM_X4(R, addr) \
    asm volatile("ldmatrix.sync.aligned.m8n8.x4.shared.b16 {%0,%1,%2,%3}, [%4];" \
                 : "=r"((R)[0]), "=r"((R)[1]), "=r"((R)[2]), "=r"((R)[3]) : "r"(addr))

__device__ __forceinline__ void mma_bf16(float* c, const uint32_t* a,
                                         uint32_t b0, uint32_t b1) {
    asm volatile(
        "mma.sync.aligned.m16n8k16.row.col.f32.bf16.bf16.f32 "
        "{%0,%1,%2,%3}, {%4,%5,%6,%7}, {%8,%9}, {%0,%1,%2,%3};"
        : "+f"(c[0]), "+f"(c[1]), "+f"(c[2]), "+f"(c[3])
        : "r"(a[0]), "r"(a[1]), "r"(a[2]), "r"(a[3]), "r"(b0), "r"(b1));
}

__device__ __forceinline__ void cp16(uint32_t s, const void* g) {
    asm volatile("cp.async.cg.shared.global [%0], [%1], 16;" :: "r"(s), "l"(g));
}
#define CP_COMMIT() asm volatile("cp.async.commit_group;" ::: "memory")
#define CP_WAIT1()  asm volatile("cp.async.wait_group 1;"  ::: "memory")
#define CP_WAIT0()  asm volatile("cp.async.wait_group 0;"  ::: "memory")

__device__ __forceinline__ void split_bf16(float v, bf16& h, bf16& m) {
    h = __float2bfloat16(v);
    m = __float2bfloat16(v - __bfloat162float(h));
}

// 64B-row swizzle: 16B chunk index XORed with row bits [2:1] -> conflict-free LDSM
__device__ __forceinline__ uint32_t swz64(int r, int ch) {
    return (uint32_t)(r * 64 + (((unsigned)ch ^ (((unsigned)r >> 1) & 3u)) << 4));
}

// ---------------------------------------------------------------------------
// smem layout: 3 stages x 32KB. Each stage: Ah(8K) Am(8K) Bh(8K) Bm(8K).
// ---------------------------------------------------------------------------
#define STAGE_B   32768
#define OFF_AM    8192
#define OFF_BH    16384
#define OFF_BM    24576
#define SMEM_GEMM (3 * STAGE_B)   // 98304; 2 CTAs/SM -> 192KB < 228KB

// C(128x128 fp32 regs) += 3xBF16-split A(128xK) . B(128xK)^T
// 8 warps, warp grid 4(m) x 2(n), warp tile 32x64. 3-stage cp.async ring.
// Per-thread global pointers advance by 32 elems per issued stage (no per-chunk
// address recompute).
__device__ __forceinline__ void gemm_mainloop(
    uint32_t sb,
    const bf16* __restrict__ Ah, const bf16* __restrict__ Am, int lda,
    const bf16* __restrict__ Bh, const bf16* __restrict__ Bm, int ldb,
    int chunks, float (&acc)[2][8][4])
{
#pragma unroll
    for (int a = 0; a < 2; a++)
#pragma unroll
        for (int b = 0; b < 8; b++)
#pragma unroll
            for (int cc = 0; cc < 4; cc++) acc[a][b][cc] = 0.f;

    const int tid = threadIdx.x, lane = tid & 31, wid = tid >> 5;
    const int wm = wid >> 1, wn = wid & 1;

    // ldmatrix lane->address mapping
    const int rA = wm * 32 + (lane & 15);                        // + mb*16
    const int hA = lane >> 4;                                    // k-half
    const int rB = wn * 64 + (lane & 7) + ((lane >> 4) & 1) * 8; // + nb*16
    const int hB = (lane >> 3) & 1;

    // loader state (each thread: row r, chunks c0 and c0+1)
    const int r  = tid >> 1;
    const int c0 = (tid & 1) * 2;
    const uint32_t so0 = swz64(r, c0);
    const uint32_t so1 = swz64(r, c0 + 1);
    const bf16* pAh = Ah + (size_t)r * lda + c0 * 8;
    const bf16* pAm = Am + (size_t)r * lda + c0 * 8;
    const bf16* pBh = Bh + (size_t)r * ldb + c0 * 8;
    const bf16* pBm = Bm + (size_t)r * ldb + c0 * 8;

#define ISSUE_STAGE(SBUF) do {                          \
        const uint32_t _b = (SBUF);                     \
        cp16(_b + so0,          pAh);                   \
        cp16(_b + so1,          pAh + 8);               \
        cp16(_b + OFF_AM + so0, pAm);                   \
        cp16(_b + OFF_AM + so1, pAm + 8);               \
        cp16(_b + OFF_BH + so0, pBh);                   \
        cp16(_b + OFF_BH + so1, pBh + 8);               \
        cp16(_b + OFF_BM + so0, pBm);                   \
        cp16(_b + OFF_BM + so1, pBm + 8);               \
        pAh += 32; pAm += 32; pBh += 32; pBm += 32;     \
        CP_COMMIT();                                    \
    } while (0)

    ISSUE_STAGE(sb);
    ISSUE_STAGE(sb + STAGE_B);

    int stage = 0;         // stage index of chunk c
    int pstage = 2;        // stage index of chunk c+2
    for (int c = 0; c < chunks; c++) {
        if (c + 1 < chunks) CP_WAIT1(); else CP_WAIT0();
        __syncthreads();   // data visible AND all warps done with stage pstage
        if (c + 2 < chunks) ISSUE_STAGE(sb + pstage * STAGE_B);
        const uint32_t buf = sb + stage * STAGE_B;
#pragma unroll
        for (int k16 = 0; k16 < 2; k16++) {
            uint32_t aH[2][4], aM[2][4];
#pragma unroll
            for (int mb = 0; mb < 2; mb++) {
                const uint32_t off = swz64(rA + mb * 16, k16 * 2 + hA);
                LDSM_X4(aH[mb], buf + off);
                LDSM_X4(aM[mb], buf + OFF_AM + off);
            }
#pragma unroll
            for (int nb = 0; nb < 4; nb++) {
                const uint32_t offB = swz64(rB + nb * 16, k16 * 2 + hB);
                uint32_t bH[4], bM[4];
                LDSM_X4(bH, buf + OFF_BH + offB);
                LDSM_X4(bM, buf + OFF_BM + offB);
#pragma unroll
                for (int mb = 0; mb < 2; mb++) {
                    mma_bf16(acc[mb][nb * 2 + 0], aH[mb], bH[0], bH[1]);
                    mma_bf16(acc[mb][nb * 2 + 1], aH[mb], bH[2], bH[3]);
                    mma_bf16(acc[mb][nb * 2 + 0], aH[mb], bM[0], bM[1]);
                    mma_bf16(acc[mb][nb * 2 + 1], aH[mb], bM[2], bM[3]);
                    mma_bf16(acc[mb][nb * 2 + 0], aM[mb], bH[0], bH[1]);
                    mma_bf16(acc[mb][nb * 2 + 1], aM[mb], bH[2], bH[3]);
                }
            }
        }
        stage = (stage == 2) ? 0 : stage + 1;
        pstage = (pstage == 2) ? 0 : pstage + 1;
    }
    __syncthreads();
#undef ISSUE_STAGE
}

// Epilogue coordinates: acc[mb][j][reg]
//   row_local = wm*32 + mb*16 + (lane>>2) + (reg>=2)*8
//   col_local = wn*64 + j*8 + (lane&3)*2 + (reg&1)

// ---------------------------------------------------------------------------
// Kernel: fp32 -> (hi, mid) bf16 split conversion
// ---------------------------------------------------------------------------
__global__ void __launch_bounds__(256)
k_convert(const float* __restrict__ in, int sel, long n4) {
    bf16 *H, *M;
    if (sel == 0) { H = g_Hh; M = g_Hm; }
    else          { H = g_Wh4[sel - 1]; M = g_Wm4[sel - 1]; }
    long i = (long)blockIdx.x * blockDim.x + threadIdx.x;
    if (i >= n4) return;
    float4 v = ((const float4*)in)[i];
    alignas(8) bf16 h[4], m[4];
    split_bf16(v.x, h[0], m[0]);
    split_bf16(v.y, h[1], m[1]);
    split_bf16(v.z, h[2], m[2]);
    split_bf16(v.w, h[3], m[3]);
    *(uint2*)(H + i * 4) = *(const uint2*)h;
    *(uint2*)(M + i * 4) = *(const uint2*)m;
}

// ---------------------------------------------------------------------------
// Kernel: Q/K/V projection, all three in one launch.
// grid (nt=16 [head], mt=64, which=3), block 256.
// ---------------------------------------------------------------------------
__global__ void __launch_bounds__(256, 2)
k_proj(void) {
    extern __shared__ char sm[];
    const uint32_t sb = smem_u32(sm);
    const int nt = blockIdx.x, mt = blockIdx.y, which = blockIdx.z;

    float acc[2][8][4];
    gemm_mainloop(sb,
        g_Hh + (size_t)mt * 128 * DM, g_Hm + (size_t)mt * 128 * DM, DM,
        g_Wh4[which] + (size_t)nt * 128 * DM, g_Wm4[which] + (size_t)nt * 128 * DM, DM,
        DM / 32, acc);

    bf16 *Gh, *Gm;
    if (which == 0)      { Gh = g_Qh; Gm = g_Qm; }
    else if (which == 1) { Gh = g_Kh; Gm = g_Km; }
    else                 { Gh = g_Vh; Gm = g_Vm; }

    const int tid = threadIdx.x, lane = tid & 31, wid = tid >> 5;
    const int wm = wid >> 1, wn = wid & 1;
#pragma unroll
    for (int mb = 0; mb < 2; mb++)
#pragma unroll
        for (int rp = 0; rp < 2; rp++) {
            const int m = mt * 128 + wm * 32 + mb * 16 + (lane >> 2) + rp * 8;
            const int b = m >> 11, s = m & (SEQ - 1);
            bf16* ph = Gh + ((size_t)(b * NH + nt) * SEQ + s) * DH;
            bf16* pm = Gm + ((size_t)(b * NH + nt) * SEQ + s) * DH;
#pragma unroll
            for (int j = 0; j < 8; j++) {
                const int col = wn * 64 + j * 8 + (lane & 3) * 2;
                bf16 h0, m0, h1, m1;
                split_bf16(acc[mb][j][rp * 2 + 0], h0, m0);
                split_bf16(acc[mb][j][rp * 2 + 1], h1, m1);
                *(__nv_bfloat162*)(ph + col) = __nv_bfloat162(h0, h1);
                *(__nv_bfloat162*)(pm + col) = __nv_bfloat162(m0, m1);
            }
        }
}

// ---------------------------------------------------------------------------
// Kernel: transpose V [bh,s,dh] -> [bh,dh,s] (both splits)
// ---------------------------------------------------------------------------
__global__ void __launch_bounds__(256)
k_transpose() {
    __shared__ bf16 tile[32][33];
    const int d0 = blockIdx.x * 32;
    const int s0 = blockIdx.y * 32;
    const int bh = blockIdx.z;
    const int tx = threadIdx.x, ty = threadIdx.y;
#pragma unroll
    for (int p = 0; p < 2; p++) {
        const bf16* src = p ? g_Vm : g_Vh;
        bf16* dst = p ? g_Vtm : g_Vth;
#pragma unroll
        for (int r = 0; r < 4; r++)
            tile[ty + r * 8][tx] =
                src[(size_t)bh * SEQ * DH + (size_t)(s0 + ty + r * 8) * DH + d0 + tx];
        __syncthreads();
#pragma unroll
        for (int r = 0; r < 4; r++)
            dst[(size_t)bh * DH * SEQ + (size_t)(d0 + ty + r * 8) * SEQ + s0 + tx] =
                tile[tx][ty + r * 8];
        __syncthreads();
    }
}

// ---------------------------------------------------------------------------
// Kernel: causal scores = Q . K^T (fp32 to g_S). Triangular launch:
// grid (t=136, bh=64); t decodes to (bi, bj) with bj <= bi.
// ---------------------------------------------------------------------------
__global__ void __launch_bounds__(256, 2)
k_scores() {
    const int t = blockIdx.x;
    int bi = (int)((sqrtf(8.f * (float)t + 1.f) - 1.f) * 0.5f);
    if ((bi + 1) * (bi + 2) / 2 <= t) bi++;
    else if (bi * (bi + 1) / 2 > t) bi--;
    const int bj = t - bi * (bi + 1) / 2;
    const int bh = blockIdx.y;

    extern __shared__ char sm[];
    const uint32_t sb = smem_u32(sm);

    const size_t hb = (size_t)bh * SEQ * DH;
    float acc[2][8][4];
    gemm_mainloop(sb,
        g_Qh + hb + (size_t)bi * 128 * DH, g_Qm + hb + (size_t)bi * 128 * DH, DH,
        g_Kh + hb + (size_t)bj * 128 * DH, g_Km + hb + (size_t)bj * 128 * DH, DH,
        DH / 32, acc);

    const int tid = threadIdx.x, lane = tid & 31, wid = tid >> 5;
    const int wm = wid >> 1, wn = wid & 1;
    float* Sp = g_S + (size_t)bh * SEQ * SEQ;
#pragma unroll
    for (int mb = 0; mb < 2; mb++)
#pragma unroll
        for (int rp = 0; rp < 2; rp++) {
            const int m = bi * 128 + wm * 32 + mb * 16 + (lane >> 2) + rp * 8;
            float* dst = Sp + (size_t)m * SEQ + bj * 128;
#pragma unroll
            for (int j = 0; j < 8; j++) {
                const int col = wn * 64 + j * 8 + (lane & 3) * 2;
                *(float2*)(dst + col) =
                    make_float2(acc[mb][j][rp * 2], acc[mb][j][rp * 2 + 1]);
            }
        }
}

// ---------------------------------------------------------------------------
// Kernel: row softmax; each thread owns 8 CONTIGUOUS columns (vectorized).
// In-place bf16 splits into g_S row; fp32 probs to Pext when use_ext.
// ---------------------------------------------------------------------------
__device__ __forceinline__ float warp_max(float v) {
#pragma unroll
    for (int o = 16; o > 0; o >>= 1) v = fmaxf(v, __shfl_xor_sync(0xffffffffu, v, o));
    return v;
}
__device__ __forceinline__ float warp_sum(float v) {
#pragma unroll
    for (int o = 16; o > 0; o >>= 1) v += __shfl_xor_sync(0xffffffffu, v, o);
    return v;
}

__global__ void __launch_bounds__(256)
k_softmax(float* __restrict__ Pext, int use_ext) {
    __shared__ float shm[8];
    __shared__ float shs[8];

    const size_t row = blockIdx.x;
    const int q = (int)(row & (SEQ - 1));
    const float* pr = g_S + row * (size_t)SEQ;
    const int tid = threadIdx.x;
    const int wid = tid >> 5, lid = tid & 31;
    const int jb = tid * 8;                    // this thread's 8 contiguous cols

    float v[8];
    {
        float4 a = *(const float4*)(pr + jb);
        float4 b = *(const float4*)(pr + jb + 4);
        v[0] = a.x; v[1] = a.y; v[2] = a.z; v[3] = a.w;
        v[4] = b.x; v[5] = b.y; v[6] = b.z; v[7] = b.w;
    }
    float m = -CUDART_INF_F;
#pragma unroll
    for (int k = 0; k < 8; k++) {
        v[k] = (jb + k <= q) ? v[k] : -CUDART_INF_F;
        m = fmaxf(m, v[k]);
    }
    m = warp_max(m);
    if (lid == 0) shm[wid] = m;
    __syncthreads();          // also ensures all row reads precede in-place writes
    if (tid < 32) {
        float t = (tid < 8) ? shm[tid] : -CUDART_INF_F;
        t = warp_max(t);
        if (tid == 0) shm[0] = t;
    }
    __syncthreads();
    m = shm[0];

    float s = 0.f;
#pragma unroll
    for (int k = 0; k < 8; k++) {
        const float e = expf(v[k] - m);
        v[k] = e;
        s += e;
    }
    s = warp_sum(s);
    if (lid == 0) shs[wid] = s;
    __syncthreads();
    if (tid < 32) {
        float t = (tid < 8) ? shs[tid] : 0.f;
        t = warp_sum(t);
        if (tid == 0) shs[0] = t;
    }
    __syncthreads();
    const float inv = 1.f / shs[0];

#pragma unroll
    for (int k = 0; k < 8; k++) v[k] *= inv;

    if (use_ext) {
        float* po = Pext + row * (size_t)SEQ + jb;
        *(float4*)(po)     = make_float4(v[0], v[1], v[2], v[3]);
        *(float4*)(po + 4) = make_float4(v[4], v[5], v[6], v[7]);
    }

    const int jmax = ((q >> 7) + 1) << 7;      // 128-aligned; jb blocks never straddle
    if (jb < jmax) {
        bf16* ph = (bf16*)(g_S) + row * (size_t)(2 * SEQ) + jb;
        bf16* pm = ph + SEQ;
        alignas(16) bf16 h[8], md[8];
#pragma unroll
        for (int k = 0; k < 8; k++) split_bf16(v[k], h[k], md[k]);
        *(uint4*)ph = *(const uint4*)h;
        *(uint4*)pm = *(const uint4*)md;
    }
}

// ---------------------------------------------------------------------------
// Kernel: AV = P . V (causal-truncated). grid (bh=64, ybi=16), LONGEST FIRST:
// bi = 15 - ybi so 64-chunk blocks launch in wave 1, 4-chunk blocks last.
// P splits live in-place inside g_S: row stride 2*SEQ bf16, m at +SEQ.
// ---------------------------------------------------------------------------
__global__ void __launch_bounds__(256, 2)
k_av() {
    const int bh = blockIdx.x;
    const int bi = 15 - (int)blockIdx.y;
    extern __shared__ char sm[];
    const uint32_t sb = smem_u32(sm);

    const bf16* Pbase = (const bf16*)(g_S) +
                        (size_t)(bh * SEQ + bi * 128) * (size_t)(2 * SEQ);

    float acc[2][8][4];
    gemm_mainloop(sb,
        Pbase, Pbase + SEQ, 2 * SEQ,
        g_Vth + (size_t)bh * DH * SEQ,
        g_Vtm + (size_t)bh * DH * SEQ, SEQ,
        (bi + 1) * 4, acc);

    const int tid = threadIdx.x, lane = tid & 31, wid = tid >> 5;
    const int wm = wid >> 1, wn = wid & 1;
    const int b = bh >> 4, h = bh & 15;
#pragma unroll
    for (int mb = 0; mb < 2; mb++)
#pragma unroll
        for (int rp = 0; rp < 2; rp++) {
            const int s = bi * 128 + wm * 32 + mb * 16 + (lane >> 2) + rp * 8;
            bf16* ph = g_AOh + ((size_t)(b * SEQ + s)) * DM + h * 128;
            bf16* pm = g_AOm + ((size_t)(b * SEQ + s)) * DM + h * 128;
#pragma unroll
            for (int j = 0; j < 8; j++) {
                const int col = wn * 64 + j * 8 + (lane & 3) * 2;
                bf16 h0, m0, h1, m1;
                split_bf16(acc[mb][j][rp * 2 + 0], h0, m0);
                split_bf16(acc[mb][j][rp * 2 + 1], h1, m1);
                *(__nv_bfloat162*)(ph + col) = __nv_bfloat162(h0, h1);
                *(__nv_bfloat162*)(pm + col) = __nv_bfloat162(m0, m1);
            }
        }
}

// ---------------------------------------------------------------------------
// Kernel: out = AO . Wo^T + bo (fp32 to d_out). grid (nt=16, mt=64)
// ---------------------------------------------------------------------------
__global__ void __launch_bounds__(256, 2)
k_out(const float* __restrict__ bias, float* __restrict__ Out) {
    extern __shared__ char sm[];
    const uint32_t sb = smem_u32(sm);
    const int nt = blockIdx.x, mt = blockIdx.y;

    float acc[2][8][4];
    gemm_mainloop(sb,
        g_AOh + (size_t)mt * 128 * DM, g_AOm + (size_t)mt * 128 * DM, DM,
        g_Wh4[3] + (size_t)nt * 128 * DM, g_Wm4[3] + (size_t)nt * 128 * DM, DM,
        DM / 32, acc);

    const int tid = threadIdx.x, lane = tid & 31, wid = tid >> 5;
    const int wm = wid >> 1, wn = wid & 1;
#pragma unroll
    for (int mb = 0; mb < 2; mb++)
#pragma unroll
        for (int rp = 0; rp < 2; rp++) {
            const int m = mt * 128 + wm * 32 + mb * 16 + (lane >> 2) + rp * 8;
            float* dst = Out + (size_t)m * DM + nt * 128;
#pragma unroll
            for (int j = 0; j < 8; j++) {
                const int col = wn * 64 + j * 8 + (lane & 3) * 2;
                *(float2*)(dst + col) =
                    make_float2(acc[mb][j][rp * 2] + bias[nt * 128 + col],
                                acc[mb][j][rp * 2 + 1] + bias[nt * 128 + col + 1]);
            }
        }
}

// ---------------------------------------------------------------------------
// Launch
// ---------------------------------------------------------------------------
extern "C" void kernel_launch(void* const* d_in, const int* in_sizes, int n_in,
                              void* d_out, int out_size) {
    const float* hs = (const float*)d_in[0];
    const float* wq = (const float*)d_in[1];
    const float* wk = (const float*)d_in[2];
    const float* wv = (const float*)d_in[3];
    const float* wo = (const float*)d_in[4];
    const float* bo = (const float*)d_in[5];
    float* out = (float*)d_out;

    const long long OUT_ELEMS = (long long)MROWS * DM;       // 16,777,216
    const long long WEI_ELEMS = (long long)BH * SEQ * SEQ;   // 268,435,456
    const int use_ext = ((long long)out_size >= OUT_ELEMS + WEI_ELEMS) ? 1 : 0;
    float* Pext = use_ext ? (out + OUT_ELEMS) : nullptr;

    cudaFuncSetAttribute(k_proj,   cudaFuncAttributeMaxDynamicSharedMemorySize, SMEM_GEMM);
    cudaFuncSetAttribute(k_scores, cudaFuncAttributeMaxDynamicSharedMemorySize, SMEM_GEMM);
    cudaFuncSetAttribute(k_av,     cudaFuncAttributeMaxDynamicSharedMemorySize, SMEM_GEMM);
    cudaFuncSetAttribute(k_out,    cudaFuncAttributeMaxDynamicSharedMemorySize, SMEM_GEMM);

    const long nH4 = (long)MROWS * DM / 4;
    const long nW4 = (long)DM * DM / 4;
    k_convert<<<(unsigned)((nH4 + 255) / 256), 256>>>(hs, 0, nH4);
    k_convert<<<(unsigned)((nW4 + 255) / 256), 256>>>(wq, 1, nW4);
    k_convert<<<(unsigned)((nW4 + 255) / 256), 256>>>(wk, 2, nW4);
    k_convert<<<(unsigned)((nW4 + 255) / 256), 256>>>(wv, 3, nW4);
    k_convert<<<(unsigned)((nW4 + 255) / 256), 256>>>(wo, 4, nW4);

    k_proj<<<dim3(16, 64, 3), 256, SMEM_GEMM>>>();

    k_transpose<<<dim3(4, 64, BH), dim3(32, 8)>>>();

    k_scores<<<dim3(136, BH), 256, SMEM_GEMM>>>();
    k_softmax<<<BH * SEQ, 256>>>(Pext, use_ext);
    k_av<<<dim3(BH, 16), 256, SMEM_GEMM>>>();
    k_out<<<dim3(16, 64), 256, SMEM_GEMM>>>(bo, out);
}

// round 9
// speedup vs baseline: 2.8499x; 1.1012x over previous
#include <cuda_runtime.h>
#include <cuda_bf16.h>
#include <cuda_fp16.h>
#include <math_constants.h>
#include <cstdint>
#include <cstddef>

#define BATCH 4
#define NH    16
#define SEQ   2048
#define DH    128
#define DM    2048
#define BH    (BATCH*NH)     // 64
#define MROWS (BATCH*SEQ)    // 8192

typedef __nv_bfloat16 bf16;
typedef __half fp16;

// ---------------------------------------------------------------------------
// Device scratch (static globals; keep total < 2 GB for x86 link)
// ---------------------------------------------------------------------------
__device__ bf16 g_Hh[(size_t)MROWS * DM];
__device__ bf16 g_Hm[(size_t)MROWS * DM];
__device__ bf16 g_Wh3[3][(size_t)DM * DM];   // wq, wk, wv (hi)
__device__ bf16 g_Wm3[3][(size_t)DM * DM];   // wq, wk, wv (mid)
__device__ fp16 g_Wo16[(size_t)DM * DM];     // wo single fp16
__device__ bf16 g_Qh[(size_t)BH * SEQ * DH];
__device__ bf16 g_Qm[(size_t)BH * SEQ * DH];
__device__ bf16 g_Kh[(size_t)BH * SEQ * DH];
__device__ bf16 g_Km[(size_t)BH * SEQ * DH];
__device__ fp16 g_V16[(size_t)BH * SEQ * DH];    // V single fp16 [bh,s,dh]
__device__ fp16 g_Vt16[(size_t)BH * DH * SEQ];   // V^T single fp16 [bh,dh,s]
// g_S: 1 GiB. fp32 scores; softmax overwrites each 8KB row IN PLACE with
// fp16 splits: h at fp16 offsets [0,2048), m at [2048,4096).
__device__ float g_S[(size_t)BH * SEQ * SEQ];
__device__ fp16 g_AOh[(size_t)MROWS * DM];   // attn-out fp16 hi
__device__ fp16 g_AOm[(size_t)MROWS * DM];   // attn-out fp16 mid

// ---------------------------------------------------------------------------
// PTX helpers (sm_80-era: mma.sync / ldmatrix / cp.async — valid on sm_100)
// ---------------------------------------------------------------------------
__device__ __forceinline__ uint32_t smem_u32(const void* p) {
    uint32_t a;
    asm("{ .reg .u64 t; cvta.to.shared.u64 t, %1; cvt.u32.u64 %0, t; }"
        : "=r"(a) : "l"(p));
    return a;
}

#define LDSM_X4(R, addr) \
    asm volatile("ldmatrix.sync.aligned.m8n8.x4.shared.b16 {%0,%1,%2,%3}, [%4];" \
                 : "=r"((R)[0]), "=r"((R)[1]), "=r"((R)[2]), "=r"((R)[3]) : "r"(addr))

__device__ __forceinline__ void mma_bf16(float* c, const uint32_t* a,
                                         uint32_t b0, uint32_t b1) {
    asm volatile(
        "mma.sync.aligned.m16n8k16.row.col.f32.bf16.bf16.f32 "
        "{%0,%1,%2,%3}, {%4,%5,%6,%7}, {%8,%9}, {%0,%1,%2,%3};"
        : "+f"(c[0]), "+f"(c[1]), "+f"(c[2]), "+f"(c[3])
        : "r"(a[0]), "r"(a[1]), "r"(a[2]), "r"(a[3]), "r"(b0), "r"(b1));
}

__device__ __forceinline__ void mma_f16(float* c, const uint32_t* a,
                                        uint32_t b0, uint32_t b1) {
    asm volatile(
        "mma.sync.aligned.m16n8k16.row.col.f32.f16.f16.f32 "
        "{%0,%1,%2,%3}, {%4,%5,%6,%7}, {%8,%9}, {%0,%1,%2,%3};"
        : "+f"(c[0]), "+f"(c[1]), "+f"(c[2]), "+f"(c[3])
        : "r"(a[0]), "r"(a[1]), "r"(a[2]), "r"(a[3]), "r"(b0), "r"(b1));
}

__device__ __forceinline__ void cp16(uint32_t s, const void* g) {
    asm volatile("cp.async.cg.shared.global [%0], [%1], 16;" :: "r"(s), "l"(g));
}
#define CP_COMMIT() asm volatile("cp.async.commit_group;" ::: "memory")
#define CP_WAIT1()  asm volatile("cp.async.wait_group 1;"  ::: "memory")
#define CP_WAIT0()  asm volatile("cp.async.wait_group 0;"  ::: "memory")

__device__ __forceinline__ void split_bf16(float v, bf16& h, bf16& m) {
    h = __float2bfloat16(v);
    m = __float2bfloat16(v - __bfloat162float(h));
}
__device__ __forceinline__ void split_f16(float v, fp16& h, fp16& m) {
    h = __float2half(v);
    m = __float2half(v - __half2float(h));
}

// 64B-row swizzle: 16B chunk index XORed with row bits [2:1] -> conflict-free LDSM
__device__ __forceinline__ uint32_t swz64(int r, int ch) {
    return (uint32_t)(r * 64 + (((unsigned)ch ^ (((unsigned)r >> 1) & 3u)) << 4));
}

// ---------------------------------------------------------------------------
// 3-split bf16 mainloop: stage 32KB (Ah 8K, Am 8K, Bh 8K, Bm 8K), 3 stages.
// ---------------------------------------------------------------------------
#define STAGE_B    32768
#define OFF_AM     8192
#define OFF_BH     16384
#define OFF_BM     24576
#define SMEM_GEMM  (3 * STAGE_B)    // 98304

__device__ __forceinline__ void gemm_mainloop(
    uint32_t sb,
    const bf16* __restrict__ Ah, const bf16* __restrict__ Am, int lda,
    const bf16* __restrict__ Bh, const bf16* __restrict__ Bm, int ldb,
    int chunks, float (&acc)[2][8][4])
{
#pragma unroll
    for (int a = 0; a < 2; a++)
#pragma unroll
        for (int b = 0; b < 8; b++)
#pragma unroll
            for (int cc = 0; cc < 4; cc++) acc[a][b][cc] = 0.f;

    const int tid = threadIdx.x, lane = tid & 31, wid = tid >> 5;
    const int wm = wid >> 1, wn = wid & 1;

    const int rA = wm * 32 + (lane & 15);
    const int hA = lane >> 4;
    const int rB = wn * 64 + (lane & 7) + ((lane >> 4) & 1) * 8;
    const int hB = (lane >> 3) & 1;

    const int r  = tid >> 1;
    const int c0 = (tid & 1) * 2;
    const uint32_t so0 = swz64(r, c0);
    const uint32_t so1 = swz64(r, c0 + 1);
    const bf16* pAh = Ah + (size_t)r * lda + c0 * 8;
    const bf16* pAm = Am + (size_t)r * lda + c0 * 8;
    const bf16* pBh = Bh + (size_t)r * ldb + c0 * 8;
    const bf16* pBm = Bm + (size_t)r * ldb + c0 * 8;

#define ISSUE_STAGE3(SBUF) do {                         \
        const uint32_t _b = (SBUF);                     \
        cp16(_b + so0,          pAh);                   \
        cp16(_b + so1,          pAh + 8);               \
        cp16(_b + OFF_AM + so0, pAm);                   \
        cp16(_b + OFF_AM + so1, pAm + 8);               \
        cp16(_b + OFF_BH + so0, pBh);                   \
        cp16(_b + OFF_BH + so1, pBh + 8);               \
        cp16(_b + OFF_BM + so0, pBm);                   \
        cp16(_b + OFF_BM + so1, pBm + 8);               \
        pAh += 32; pAm += 32; pBh += 32; pBm += 32;     \
        CP_COMMIT();                                    \
    } while (0)

    ISSUE_STAGE3(sb);
    ISSUE_STAGE3(sb + STAGE_B);

    int stage = 0, pstage = 2;
    for (int c = 0; c < chunks; c++) {
        if (c + 1 < chunks) CP_WAIT1(); else CP_WAIT0();
        __syncthreads();
        if (c + 2 < chunks) ISSUE_STAGE3(sb + pstage * STAGE_B);
        const uint32_t buf = sb + stage * STAGE_B;
#pragma unroll
        for (int k16 = 0; k16 < 2; k16++) {
            uint32_t aH[2][4], aM[2][4];
#pragma unroll
            for (int mb = 0; mb < 2; mb++) {
                const uint32_t off = swz64(rA + mb * 16, k16 * 2 + hA);
                LDSM_X4(aH[mb], buf + off);
                LDSM_X4(aM[mb], buf + OFF_AM + off);
            }
#pragma unroll
            for (int nb = 0; nb < 4; nb++) {
                const uint32_t offB = swz64(rB + nb * 16, k16 * 2 + hB);
                uint32_t bH[4], bM[4];
                LDSM_X4(bH, buf + OFF_BH + offB);
                LDSM_X4(bM, buf + OFF_BM + offB);
#pragma unroll
                for (int mb = 0; mb < 2; mb++) {
                    mma_bf16(acc[mb][nb * 2 + 0], aH[mb], bH[0], bH[1]);
                    mma_bf16(acc[mb][nb * 2 + 1], aH[mb], bH[2], bH[3]);
                    mma_bf16(acc[mb][nb * 2 + 0], aH[mb], bM[0], bM[1]);
                    mma_bf16(acc[mb][nb * 2 + 1], aH[mb], bM[2], bM[3]);
                    mma_bf16(acc[mb][nb * 2 + 0], aM[mb], bH[0], bH[1]);
                    mma_bf16(acc[mb][nb * 2 + 1], aM[mb], bH[2], bH[3]);
                }
            }
        }
        stage = (stage == 2) ? 0 : stage + 1;
        pstage = (pstage == 2) ? 0 : pstage + 1;
    }
    __syncthreads();
#undef ISSUE_STAGE3
}

// ---------------------------------------------------------------------------
// fp16 2x1 mainloop: A = Ah+Am (fp16 2-split), B single fp16. 2 MMAs/step.
// Stage 24KB (Ah 8K, Am 8K, B 8K), 3 stages.
// ---------------------------------------------------------------------------
#define STAGE21_B   24576
#define OFF21_AM    8192
#define OFF21_B     16384
#define SMEM_GEMM21 (3 * STAGE21_B)   // 73728

__device__ __forceinline__ void gemm_mainloop_21(
    uint32_t sb,
    const fp16* __restrict__ Ah, const fp16* __restrict__ Am, int lda,
    const fp16* __restrict__ B, int ldb,
    int chunks, float (&acc)[2][8][4])
{
#pragma unroll
    for (int a = 0; a < 2; a++)
#pragma unroll
        for (int b = 0; b < 8; b++)
#pragma unroll
            for (int cc = 0; cc < 4; cc++) acc[a][b][cc] = 0.f;

    const int tid = threadIdx.x, lane = tid & 31, wid = tid >> 5;
    const int wm = wid >> 1, wn = wid & 1;

    const int rA = wm * 32 + (lane & 15);
    const int hA = lane >> 4;
    const int rB = wn * 64 + (lane & 7) + ((lane >> 4) & 1) * 8;
    const int hB = (lane >> 3) & 1;

    const int r  = tid >> 1;
    const int c0 = (tid & 1) * 2;
    const uint32_t so0 = swz64(r, c0);
    const uint32_t so1 = swz64(r, c0 + 1);
    const fp16* pAh = Ah + (size_t)r * lda + c0 * 8;
    const fp16* pAm = Am + (size_t)r * lda + c0 * 8;
    const fp16* pB  = B  + (size_t)r * ldb + c0 * 8;

#define ISSUE_STAGE21(SBUF) do {                        \
        const uint32_t _b = (SBUF);                     \
        cp16(_b + so0,           pAh);                  \
        cp16(_b + so1,           pAh + 8);              \
        cp16(_b + OFF21_AM + so0, pAm);                 \
        cp16(_b + OFF21_AM + so1, pAm + 8);             \
        cp16(_b + OFF21_B + so0,  pB);                  \
        cp16(_b + OFF21_B + so1,  pB + 8);              \
        pAh += 32; pAm += 32; pB += 32;                 \
        CP_COMMIT();                                    \
    } while (0)

    ISSUE_STAGE21(sb);
    ISSUE_STAGE21(sb + STAGE21_B);

    int stage = 0, pstage = 2;
    for (int c = 0; c < chunks; c++) {
        if (c + 1 < chunks) CP_WAIT1(); else CP_WAIT0();
        __syncthreads();
        if (c + 2 < chunks) ISSUE_STAGE21(sb + pstage * STAGE21_B);
        const uint32_t buf = sb + stage * STAGE21_B;
#pragma unroll
        for (int k16 = 0; k16 < 2; k16++) {
            uint32_t aH[2][4], aM[2][4];
#pragma unroll
            for (int mb = 0; mb < 2; mb++) {
                const uint32_t off = swz64(rA + mb * 16, k16 * 2 + hA);
                LDSM_X4(aH[mb], buf + off);
                LDSM_X4(aM[mb], buf + OFF21_AM + off);
            }
#pragma unroll
            for (int nb = 0; nb < 4; nb++) {
                const uint32_t offB = swz64(rB + nb * 16, k16 * 2 + hB);
                uint32_t bV[4];
                LDSM_X4(bV, buf + OFF21_B + offB);
#pragma unroll
                for (int mb = 0; mb < 2; mb++) {
                    mma_f16(acc[mb][nb * 2 + 0], aH[mb], bV[0], bV[1]);
                    mma_f16(acc[mb][nb * 2 + 1], aH[mb], bV[2], bV[3]);
                    mma_f16(acc[mb][nb * 2 + 0], aM[mb], bV[0], bV[1]);
                    mma_f16(acc[mb][nb * 2 + 1], aM[mb], bV[2], bV[3]);
                }
            }
        }
        stage = (stage == 2) ? 0 : stage + 1;
        pstage = (pstage == 2) ? 0 : pstage + 1;
    }
    __syncthreads();
#undef ISSUE_STAGE21
}

// Epilogue coordinates: acc[mb][j][reg]
//   row_local = wm*32 + mb*16 + (lane>>2) + (reg>=2)*8
//   col_local = wn*64 + j*8 + (lane&3)*2 + (reg&1)

// ---------------------------------------------------------------------------
// Kernel: input conversions. sel: 0=hidden(bf16 split), 1..3=wq,wk,wv(bf16
// split), 4=wo(fp16 single)
// ---------------------------------------------------------------------------
__global__ void __launch_bounds__(256)
k_convert(const float* __restrict__ in, int sel, long n4) {
    long i = (long)blockIdx.x * blockDim.x + threadIdx.x;
    if (i >= n4) return;
    float4 v = ((const float4*)in)[i];
    if (sel == 4) {
        alignas(8) fp16 h[4];
        h[0] = __float2half(v.x); h[1] = __float2half(v.y);
        h[2] = __float2half(v.z); h[3] = __float2half(v.w);
        *(uint2*)(g_Wo16 + i * 4) = *(const uint2*)h;
        return;
    }
    bf16 *H, *M;
    if (sel == 0) { H = g_Hh; M = g_Hm; }
    else          { H = g_Wh3[sel - 1]; M = g_Wm3[sel - 1]; }
    alignas(8) bf16 h[4], m[4];
    split_bf16(v.x, h[0], m[0]);
    split_bf16(v.y, h[1], m[1]);
    split_bf16(v.z, h[2], m[2]);
    split_bf16(v.w, h[3], m[3]);
    *(uint2*)(H + i * 4) = *(const uint2*)h;
    *(uint2*)(M + i * 4) = *(const uint2*)m;
}

// ---------------------------------------------------------------------------
// Kernel: Q/K/V projection (bf16 3-split GEMM for all three; epilogue
// differs: Q,K -> bf16 splits, V -> single fp16). grid (nt, mt, which=3).
// ---------------------------------------------------------------------------
__global__ void __launch_bounds__(256, 2)
k_proj(void) {
    extern __shared__ char sm[];
    const uint32_t sb = smem_u32(sm);
    const int nt = blockIdx.x, mt = blockIdx.y, which = blockIdx.z;

    float acc[2][8][4];
    gemm_mainloop(sb,
        g_Hh + (size_t)mt * 128 * DM, g_Hm + (size_t)mt * 128 * DM, DM,
        g_Wh3[which] + (size_t)nt * 128 * DM, g_Wm3[which] + (size_t)nt * 128 * DM, DM,
        DM / 32, acc);

    const int tid = threadIdx.x, lane = tid & 31, wid = tid >> 5;
    const int wm = wid >> 1, wn = wid & 1;

    if (which == 2) {  // V -> single fp16
#pragma unroll
        for (int mb = 0; mb < 2; mb++)
#pragma unroll
            for (int rp = 0; rp < 2; rp++) {
                const int m = mt * 128 + wm * 32 + mb * 16 + (lane >> 2) + rp * 8;
                const int b = m >> 11, s = m & (SEQ - 1);
                fp16* pv = g_V16 + ((size_t)(b * NH + nt) * SEQ + s) * DH;
#pragma unroll
                for (int j = 0; j < 8; j++) {
                    const int col = wn * 64 + j * 8 + (lane & 3) * 2;
                    __half2 hv = __floats2half2_rn(acc[mb][j][rp * 2 + 0],
                                                   acc[mb][j][rp * 2 + 1]);
                    *(__half2*)(pv + col) = hv;
                }
            }
        return;
    }

    bf16* Gh = (which == 0) ? g_Qh : g_Kh;
    bf16* Gm = (which == 0) ? g_Qm : g_Km;
#pragma unroll
    for (int mb = 0; mb < 2; mb++)
#pragma unroll
        for (int rp = 0; rp < 2; rp++) {
            const int m = mt * 128 + wm * 32 + mb * 16 + (lane >> 2) + rp * 8;
            const int b = m >> 11, s = m & (SEQ - 1);
            bf16* ph = Gh + ((size_t)(b * NH + nt) * SEQ + s) * DH;
            bf16* pm = Gm + ((size_t)(b * NH + nt) * SEQ + s) * DH;
#pragma unroll
            for (int j = 0; j < 8; j++) {
                const int col = wn * 64 + j * 8 + (lane & 3) * 2;
                bf16 h0, m0, h1, m1;
                split_bf16(acc[mb][j][rp * 2 + 0], h0, m0);
                split_bf16(acc[mb][j][rp * 2 + 1], h1, m1);
                *(__nv_bfloat162*)(ph + col) = __nv_bfloat162(h0, h1);
                *(__nv_bfloat162*)(pm + col) = __nv_bfloat162(m0, m1);
            }
        }
}

// ---------------------------------------------------------------------------
// Kernel: transpose V [bh,s,dh] -> [bh,dh,s] (single fp16)
// ---------------------------------------------------------------------------
__global__ void __launch_bounds__(256)
k_transpose() {
    __shared__ fp16 tile[32][33];
    const int d0 = blockIdx.x * 32;
    const int s0 = blockIdx.y * 32;
    const int bh = blockIdx.z;
    const int tx = threadIdx.x, ty = threadIdx.y;
#pragma unroll
    for (int r = 0; r < 4; r++)
        tile[ty + r * 8][tx] =
            g_V16[(size_t)bh * SEQ * DH + (size_t)(s0 + ty + r * 8) * DH + d0 + tx];
    __syncthreads();
#pragma unroll
    for (int r = 0; r < 4; r++)
        g_Vt16[(size_t)bh * DH * SEQ + (size_t)(d0 + ty + r * 8) * SEQ + s0 + tx] =
            tile[tx][ty + r * 8];
}

// ---------------------------------------------------------------------------
// Kernel: causal scores = Q . K^T (fp32 to g_S). Triangular launch.
// ---------------------------------------------------------------------------
__global__ void __launch_bounds__(256, 2)
k_scores() {
    const int t = blockIdx.x;
    int bi = (int)((sqrtf(8.f * (float)t + 1.f) - 1.f) * 0.5f);
    if ((bi + 1) * (bi + 2) / 2 <= t) bi++;
    else if (bi * (bi + 1) / 2 > t) bi--;
    const int bj = t - bi * (bi + 1) / 2;
    const int bh = blockIdx.y;

    extern __shared__ char sm[];
    const uint32_t sb = smem_u32(sm);

    const size_t hb = (size_t)bh * SEQ * DH;
    float acc[2][8][4];
    gemm_mainloop(sb,
        g_Qh + hb + (size_t)bi * 128 * DH, g_Qm + hb + (size_t)bi * 128 * DH, DH,
        g_Kh + hb + (size_t)bj * 128 * DH, g_Km + hb + (size_t)bj * 128 * DH, DH,
        DH / 32, acc);

    const int tid = threadIdx.x, lane = tid & 31, wid = tid >> 5;
    const int wm = wid >> 1, wn = wid & 1;
    float* Sp = g_S + (size_t)bh * SEQ * SEQ;
#pragma unroll
    for (int mb = 0; mb < 2; mb++)
#pragma unroll
        for (int rp = 0; rp < 2; rp++) {
            const int m = bi * 128 + wm * 32 + mb * 16 + (lane >> 2) + rp * 8;
            float* dst = Sp + (size_t)m * SEQ + bj * 128;
#pragma unroll
            for (int j = 0; j < 8; j++) {
                const int col = wn * 64 + j * 8 + (lane & 3) * 2;
                *(float2*)(dst + col) =
                    make_float2(acc[mb][j][rp * 2], acc[mb][j][rp * 2 + 1]);
            }
        }
}

// ---------------------------------------------------------------------------
// Kernel: row softmax (vectorized, 8 contiguous cols/thread). In-place fp16
// splits into the g_S row; fp32 probs to Pext when use_ext.
// ---------------------------------------------------------------------------
__device__ __forceinline__ float warp_max(float v) {
#pragma unroll
    for (int o = 16; o > 0; o >>= 1) v = fmaxf(v, __shfl_xor_sync(0xffffffffu, v, o));
    return v;
}
__device__ __forceinline__ float warp_sum(float v) {
#pragma unroll
    for (int o = 16; o > 0; o >>= 1) v += __shfl_xor_sync(0xffffffffu, v, o);
    return v;
}

__global__ void __launch_bounds__(256)
k_softmax(float* __restrict__ Pext, int use_ext) {
    __shared__ float shm[8];
    __shared__ float shs[8];

    const size_t row = blockIdx.x;
    const int q = (int)(row & (SEQ - 1));
    const float* pr = g_S + row * (size_t)SEQ;
    const int tid = threadIdx.x;
    const int wid = tid >> 5, lid = tid & 31;
    const int jb = tid * 8;

    float v[8];
    {
        float4 a = *(const float4*)(pr + jb);
        float4 b = *(const float4*)(pr + jb + 4);
        v[0] = a.x; v[1] = a.y; v[2] = a.z; v[3] = a.w;
        v[4] = b.x; v[5] = b.y; v[6] = b.z; v[7] = b.w;
    }
    float m = -CUDART_INF_F;
#pragma unroll
    for (int k = 0; k < 8; k++) {
        v[k] = (jb + k <= q) ? v[k] : -CUDART_INF_F;
        m = fmaxf(m, v[k]);
    }
    m = warp_max(m);
    if (lid == 0) shm[wid] = m;
    __syncthreads();          // all row reads precede in-place writes
    if (tid < 32) {
        float t = (tid < 8) ? shm[tid] : -CUDART_INF_F;
        t = warp_max(t);
        if (tid == 0) shm[0] = t;
    }
    __syncthreads();
    m = shm[0];

    float s = 0.f;
#pragma unroll
    for (int k = 0; k < 8; k++) {
        const float e = expf(v[k] - m);
        v[k] = e;
        s += e;
    }
    s = warp_sum(s);
    if (lid == 0) shs[wid] = s;
    __syncthreads();
    if (tid < 32) {
        float t = (tid < 8) ? shs[tid] : 0.f;
        t = warp_sum(t);
        if (tid == 0) shs[0] = t;
    }
    __syncthreads();
    const float inv = 1.f / shs[0];

#pragma unroll
    for (int k = 0; k < 8; k++) v[k] *= inv;

    if (use_ext) {
        float* po = Pext + row * (size_t)SEQ + jb;
        *(float4*)(po)     = make_float4(v[0], v[1], v[2], v[3]);
        *(float4*)(po + 4) = make_float4(v[4], v[5], v[6], v[7]);
    }

    const int jmax = ((q >> 7) + 1) << 7;      // 128-aligned
    if (jb < jmax) {
        fp16* ph = (fp16*)(g_S) + row * (size_t)(2 * SEQ) + jb;
        fp16* pm = ph + SEQ;
        alignas(16) fp16 h[8], md[8];
#pragma unroll
        for (int k = 0; k < 8; k++) split_f16(v[k], h[k], md[k]);
        *(uint4*)ph = *(const uint4*)h;
        *(uint4*)pm = *(const uint4*)md;
    }
}

// ---------------------------------------------------------------------------
// Kernel: AV = P . V (fp16 2x1, causal-truncated). grid (bh=64, ybi=16),
// longest-first. Epilogue: fp16 2-split into g_AOh/g_AOm.
// ---------------------------------------------------------------------------
__global__ void __launch_bounds__(256, 2)
k_av() {
    const int bh = blockIdx.x;
    const int bi = 15 - (int)blockIdx.y;
    extern __shared__ char sm[];
    const uint32_t sb = smem_u32(sm);

    const fp16* Pbase = (const fp16*)(g_S) +
                        (size_t)(bh * SEQ + bi * 128) * (size_t)(2 * SEQ);

    float acc[2][8][4];
    gemm_mainloop_21(sb,
        Pbase, Pbase + SEQ, 2 * SEQ,
        g_Vt16 + (size_t)bh * DH * SEQ, SEQ,
        (bi + 1) * 4, acc);

    const int tid = threadIdx.x, lane = tid & 31, wid = tid >> 5;
    const int wm = wid >> 1, wn = wid & 1;
    const int b = bh >> 4, h = bh & 15;
#pragma unroll
    for (int mb = 0; mb < 2; mb++)
#pragma unroll
        for (int rp = 0; rp < 2; rp++) {
            const int s = bi * 128 + wm * 32 + mb * 16 + (lane >> 2) + rp * 8;
            fp16* ph = g_AOh + ((size_t)(b * SEQ + s)) * DM + h * 128;
            fp16* pm = g_AOm + ((size_t)(b * SEQ + s)) * DM + h * 128;
#pragma unroll
            for (int j = 0; j < 8; j++) {
                const int col = wn * 64 + j * 8 + (lane & 3) * 2;
                fp16 h0, m0, h1, m1;
                split_f16(acc[mb][j][rp * 2 + 0], h0, m0);
                split_f16(acc[mb][j][rp * 2 + 1], h1, m1);
                *(__half2*)(ph + col) = __half2(h0, h1);
                *(__half2*)(pm + col) = __half2(m0, m1);
            }
        }
}

// ---------------------------------------------------------------------------
// Kernel: out = AO . Wo^T + bo (fp16 2x1, fp32 to d_out). grid (nt, mt)
// ---------------------------------------------------------------------------
__global__ void __launch_bounds__(256, 2)
k_out(const float* __restrict__ bias, float* __restrict__ Out) {
    extern __shared__ char sm[];
    const uint32_t sb = smem_u32(sm);
    const int nt = blockIdx.x, mt = blockIdx.y;

    float acc[2][8][4];
    gemm_mainloop_21(sb,
        g_AOh + (size_t)mt * 128 * DM, g_AOm + (size_t)mt * 128 * DM, DM,
        g_Wo16 + (size_t)nt * 128 * DM, DM,
        DM / 32, acc);

    const int tid = threadIdx.x, lane = tid & 31, wid = tid >> 5;
    const int wm = wid >> 1, wn = wid & 1;
#pragma unroll
    for (int mb = 0; mb < 2; mb++)
#pragma unroll
        for (int rp = 0; rp < 2; rp++) {
            const int m = mt * 128 + wm * 32 + mb * 16 + (lane >> 2) + rp * 8;
            float* dst = Out + (size_t)m * DM + nt * 128;
#pragma unroll
            for (int j = 0; j < 8; j++) {
                const int col = wn * 64 + j * 8 + (lane & 3) * 2;
                *(float2*)(dst + col) =
                    make_float2(acc[mb][j][rp * 2] + bias[nt * 128 + col],
                                acc[mb][j][rp * 2 + 1] + bias[nt * 128 + col + 1]);
            }
        }
}

// ---------------------------------------------------------------------------
// Launch
// ---------------------------------------------------------------------------
extern "C" void kernel_launch(void* const* d_in, const int* in_sizes, int n_in,
                              void* d_out, int out_size) {
    const float* hs = (const float*)d_in[0];
    const float* wq = (const float*)d_in[1];
    const float* wk = (const float*)d_in[2];
    const float* wv = (const float*)d_in[3];
    const float* wo = (const float*)d_in[4];
    const float* bo = (const float*)d_in[5];
    float* out = (float*)d_out;

    const long long OUT_ELEMS = (long long)MROWS * DM;       // 16,777,216
    const long long WEI_ELEMS = (long long)BH * SEQ * SEQ;   // 268,435,456
    const int use_ext = ((long long)out_size >= OUT_ELEMS + WEI_ELEMS) ? 1 : 0;
    float* Pext = use_ext ? (out + OUT_ELEMS) : nullptr;

    cudaFuncSetAttribute(k_proj,   cudaFuncAttributeMaxDynamicSharedMemorySize, SMEM_GEMM);
    cudaFuncSetAttribute(k_scores, cudaFuncAttributeMaxDynamicSharedMemorySize, SMEM_GEMM);
    cudaFuncSetAttribute(k_av,     cudaFuncAttributeMaxDynamicSharedMemorySize, SMEM_GEMM21);
    cudaFuncSetAttribute(k_out,    cudaFuncAttributeMaxDynamicSharedMemorySize, SMEM_GEMM21);

    const long nH4 = (long)MROWS * DM / 4;
    const long nW4 = (long)DM * DM / 4;
    k_convert<<<(unsigned)((nH4 + 255) / 256), 256>>>(hs, 0, nH4);
    k_convert<<<(unsigned)((nW4 + 255) / 256), 256>>>(wq, 1, nW4);
    k_convert<<<(unsigned)((nW4 + 255) / 256), 256>>>(wk, 2, nW4);
    k_convert<<<(unsigned)((nW4 + 255) / 256), 256>>>(wv, 3, nW4);
    k_convert<<<(unsigned)((nW4 + 255) / 256), 256>>>(wo, 4, nW4);

    k_proj<<<dim3(16, 64, 3), 256, SMEM_GEMM>>>();

    k_transpose<<<dim3(4, 64, BH), dim3(32, 8)>>>();

    k_scores<<<dim3(136, BH), 256, SMEM_GEMM>>>();
    k_softmax<<<BH * SEQ, 256>>>(Pext, use_ext);
    k_av<<<dim3(BH, 16), 256, SMEM_GEMM21>>>();
    k_out<<<dim3(16, 64), 256, SMEM_GEMM21>>>(bo, out);
}

// round 10
// speedup vs baseline: 3.1616x; 1.1094x over previous
#include <cuda_runtime.h>
#include <cuda_bf16.h>
#include <cuda_fp16.h>
#include <math_constants.h>
#include <cstdint>
#include <cstddef>

#define BATCH 4
#define NH    16
#define SEQ   2048
#define DH    128
#define DM    2048
#define BH    (BATCH*NH)     // 64
#define MROWS (BATCH*SEQ)    // 8192

typedef __nv_bfloat16 bf16;
typedef __half fp16;

// ---------------------------------------------------------------------------
// Device scratch (static globals; keep total < 2 GB for x86 link)
// ---------------------------------------------------------------------------
__device__ bf16 g_Hh[(size_t)MROWS * DM];
__device__ bf16 g_Hm[(size_t)MROWS * DM];
__device__ bf16 g_Wh3[3][(size_t)DM * DM];   // wq, wk, wv (hi)
__device__ bf16 g_Wm3[3][(size_t)DM * DM];   // wq, wk, wv (mid)
__device__ fp16 g_Wo16[(size_t)DM * DM];     // wo single fp16
__device__ bf16 g_Qh[(size_t)BH * SEQ * DH];
__device__ bf16 g_Qm[(size_t)BH * SEQ * DH];
__device__ bf16 g_Kh[(size_t)BH * SEQ * DH];
__device__ bf16 g_Km[(size_t)BH * SEQ * DH];
__device__ fp16 g_V16[(size_t)BH * SEQ * DH];    // V single fp16 [bh,s,dh]
__device__ fp16 g_Vt16[(size_t)BH * DH * SEQ];   // V^T single fp16 [bh,dh,s]
// g_S: 1 GiB. fp32 scores; softmax overwrites each 8KB row IN PLACE with
// SINGLE fp16 probs at fp16 offsets [0,2048) (row stride 4096 fp16).
__device__ float g_S[(size_t)BH * SEQ * SEQ];
__device__ fp16 g_AO16[(size_t)MROWS * DM];  // attn-out single fp16

// ---------------------------------------------------------------------------
// PTX helpers (sm_80-era: mma.sync / ldmatrix / cp.async — valid on sm_100)
// ---------------------------------------------------------------------------
__device__ __forceinline__ uint32_t smem_u32(const void* p) {
    uint32_t a;
    asm("{ .reg .u64 t; cvta.to.shared.u64 t, %1; cvt.u32.u64 %0, t; }"
        : "=r"(a) : "l"(p));
    return a;
}

#define LDSM_X4(R, addr) \
    asm volatile("ldmatrix.sync.aligned.m8n8.x4.shared.b16 {%0,%1,%2,%3}, [%4];" \
                 : "=r"((R)[0]), "=r"((R)[1]), "=r"((R)[2]), "=r"((R)[3]) : "r"(addr))

__device__ __forceinline__ void mma_bf16(float* c, const uint32_t* a,
                                         uint32_t b0, uint32_t b1) {
    asm volatile(
        "mma.sync.aligned.m16n8k16.row.col.f32.bf16.bf16.f32 "
        "{%0,%1,%2,%3}, {%4,%5,%6,%7}, {%8,%9}, {%0,%1,%2,%3};"
        : "+f"(c[0]), "+f"(c[1]), "+f"(c[2]), "+f"(c[3])
        : "r"(a[0]), "r"(a[1]), "r"(a[2]), "r"(a[3]), "r"(b0), "r"(b1));
}

__device__ __forceinline__ void mma_f16(float* c, const uint32_t* a,
                                        uint32_t b0, uint32_t b1) {
    asm volatile(
        "mma.sync.aligned.m16n8k16.row.col.f32.f16.f16.f32 "
        "{%0,%1,%2,%3}, {%4,%5,%6,%7}, {%8,%9}, {%0,%1,%2,%3};"
        : "+f"(c[0]), "+f"(c[1]), "+f"(c[2]), "+f"(c[3])
        : "r"(a[0]), "r"(a[1]), "r"(a[2]), "r"(a[3]), "r"(b0), "r"(b1));
}

__device__ __forceinline__ void cp16(uint32_t s, const void* g) {
    asm volatile("cp.async.cg.shared.global [%0], [%1], 16;" :: "r"(s), "l"(g));
}
#define CP_COMMIT() asm volatile("cp.async.commit_group;" ::: "memory")
#define CP_WAIT1()  asm volatile("cp.async.wait_group 1;"  ::: "memory")
#define CP_WAIT0()  asm volatile("cp.async.wait_group 0;"  ::: "memory")

__device__ __forceinline__ void split_bf16(float v, bf16& h, bf16& m) {
    h = __float2bfloat16(v);
    m = __float2bfloat16(v - __bfloat162float(h));
}

// 64B-row swizzle: 16B chunk index XORed with row bits [2:1] -> conflict-free LDSM
__device__ __forceinline__ uint32_t swz64(int r, int ch) {
    return (uint32_t)(r * 64 + (((unsigned)ch ^ (((unsigned)r >> 1) & 3u)) << 4));
}

// ---------------------------------------------------------------------------
// 3-split bf16 mainloop: stage 32KB (Ah 8K, Am 8K, Bh 8K, Bm 8K), 3 stages.
// ---------------------------------------------------------------------------
#define STAGE_B    32768
#define OFF_AM     8192
#define OFF_BH     16384
#define OFF_BM     24576
#define SMEM_GEMM  (3 * STAGE_B)    // 98304

__device__ __forceinline__ void gemm_mainloop(
    uint32_t sb,
    const bf16* __restrict__ Ah, const bf16* __restrict__ Am, int lda,
    const bf16* __restrict__ Bh, const bf16* __restrict__ Bm, int ldb,
    int chunks, float (&acc)[2][8][4])
{
#pragma unroll
    for (int a = 0; a < 2; a++)
#pragma unroll
        for (int b = 0; b < 8; b++)
#pragma unroll
            for (int cc = 0; cc < 4; cc++) acc[a][b][cc] = 0.f;

    const int tid = threadIdx.x, lane = tid & 31, wid = tid >> 5;
    const int wm = wid >> 1, wn = wid & 1;

    const int rA = wm * 32 + (lane & 15);
    const int hA = lane >> 4;
    const int rB = wn * 64 + (lane & 7) + ((lane >> 4) & 1) * 8;
    const int hB = (lane >> 3) & 1;

    const int r  = tid >> 1;
    const int c0 = (tid & 1) * 2;
    const uint32_t so0 = swz64(r, c0);
    const uint32_t so1 = swz64(r, c0 + 1);
    const bf16* pAh = Ah + (size_t)r * lda + c0 * 8;
    const bf16* pAm = Am + (size_t)r * lda + c0 * 8;
    const bf16* pBh = Bh + (size_t)r * ldb + c0 * 8;
    const bf16* pBm = Bm + (size_t)r * ldb + c0 * 8;

#define ISSUE_STAGE3(SBUF) do {                         \
        const uint32_t _b = (SBUF);                     \
        cp16(_b + so0,          pAh);                   \
        cp16(_b + so1,          pAh + 8);               \
        cp16(_b + OFF_AM + so0, pAm);                   \
        cp16(_b + OFF_AM + so1, pAm + 8);               \
        cp16(_b + OFF_BH + so0, pBh);                   \
        cp16(_b + OFF_BH + so1, pBh + 8);               \
        cp16(_b + OFF_BM + so0, pBm);                   \
        cp16(_b + OFF_BM + so1, pBm + 8);               \
        pAh += 32; pAm += 32; pBh += 32; pBm += 32;     \
        CP_COMMIT();                                    \
    } while (0)

    ISSUE_STAGE3(sb);
    ISSUE_STAGE3(sb + STAGE_B);

    int stage = 0, pstage = 2;
    for (int c = 0; c < chunks; c++) {
        if (c + 1 < chunks) CP_WAIT1(); else CP_WAIT0();
        __syncthreads();
        if (c + 2 < chunks) ISSUE_STAGE3(sb + pstage * STAGE_B);
        const uint32_t buf = sb + stage * STAGE_B;
#pragma unroll
        for (int k16 = 0; k16 < 2; k16++) {
            uint32_t aH[2][4], aM[2][4];
#pragma unroll
            for (int mb = 0; mb < 2; mb++) {
                const uint32_t off = swz64(rA + mb * 16, k16 * 2 + hA);
                LDSM_X4(aH[mb], buf + off);
                LDSM_X4(aM[mb], buf + OFF_AM + off);
            }
#pragma unroll
            for (int nb = 0; nb < 4; nb++) {
                const uint32_t offB = swz64(rB + nb * 16, k16 * 2 + hB);
                uint32_t bH[4], bM[4];
                LDSM_X4(bH, buf + OFF_BH + offB);
                LDSM_X4(bM, buf + OFF_BM + offB);
#pragma unroll
                for (int mb = 0; mb < 2; mb++) {
                    mma_bf16(acc[mb][nb * 2 + 0], aH[mb], bH[0], bH[1]);
                    mma_bf16(acc[mb][nb * 2 + 1], aH[mb], bH[2], bH[3]);
                    mma_bf16(acc[mb][nb * 2 + 0], aH[mb], bM[0], bM[1]);
                    mma_bf16(acc[mb][nb * 2 + 1], aH[mb], bM[2], bM[3]);
                    mma_bf16(acc[mb][nb * 2 + 0], aM[mb], bH[0], bH[1]);
                    mma_bf16(acc[mb][nb * 2 + 1], aM[mb], bH[2], bH[3]);
                }
            }
        }
        stage = (stage == 2) ? 0 : stage + 1;
        pstage = (pstage == 2) ? 0 : pstage + 1;
    }
    __syncthreads();
#undef ISSUE_STAGE3
}

// ---------------------------------------------------------------------------
// fp16 1x1 mainloop: A single fp16, B single fp16. 1 MMA per (mb,nb,half).
// Stage 16KB (A 8K, B 8K), 3 stages.
// ---------------------------------------------------------------------------
#define STAGE11_B   16384
#define OFF11_B     8192
#define SMEM_GEMM11 (3 * STAGE11_B)   // 49152

__device__ __forceinline__ void gemm_mainloop_11(
    uint32_t sb,
    const fp16* __restrict__ A, int lda,
    const fp16* __restrict__ B, int ldb,
    int chunks, float (&acc)[2][8][4])
{
#pragma unroll
    for (int a = 0; a < 2; a++)
#pragma unroll
        for (int b = 0; b < 8; b++)
#pragma unroll
            for (int cc = 0; cc < 4; cc++) acc[a][b][cc] = 0.f;

    const int tid = threadIdx.x, lane = tid & 31, wid = tid >> 5;
    const int wm = wid >> 1, wn = wid & 1;

    const int rA = wm * 32 + (lane & 15);
    const int hA = lane >> 4;
    const int rB = wn * 64 + (lane & 7) + ((lane >> 4) & 1) * 8;
    const int hB = (lane >> 3) & 1;

    const int r  = tid >> 1;
    const int c0 = (tid & 1) * 2;
    const uint32_t so0 = swz64(r, c0);
    const uint32_t so1 = swz64(r, c0 + 1);
    const fp16* pA = A + (size_t)r * lda + c0 * 8;
    const fp16* pB = B + (size_t)r * ldb + c0 * 8;

#define ISSUE_STAGE11(SBUF) do {                        \
        const uint32_t _b = (SBUF);                     \
        cp16(_b + so0,           pA);                   \
        cp16(_b + so1,           pA + 8);               \
        cp16(_b + OFF11_B + so0, pB);                   \
        cp16(_b + OFF11_B + so1, pB + 8);               \
        pA += 32; pB += 32;                             \
        CP_COMMIT();                                    \
    } while (0)

    ISSUE_STAGE11(sb);
    ISSUE_STAGE11(sb + STAGE11_B);

    int stage = 0, pstage = 2;
    for (int c = 0; c < chunks; c++) {
        if (c + 1 < chunks) CP_WAIT1(); else CP_WAIT0();
        __syncthreads();
        if (c + 2 < chunks) ISSUE_STAGE11(sb + pstage * STAGE11_B);
        const uint32_t buf = sb + stage * STAGE11_B;
#pragma unroll
        for (int k16 = 0; k16 < 2; k16++) {
            uint32_t aV[2][4];
#pragma unroll
            for (int mb = 0; mb < 2; mb++) {
                const uint32_t off = swz64(rA + mb * 16, k16 * 2 + hA);
                LDSM_X4(aV[mb], buf + off);
            }
#pragma unroll
            for (int nb = 0; nb < 4; nb++) {
                const uint32_t offB = swz64(rB + nb * 16, k16 * 2 + hB);
                uint32_t bV[4];
                LDSM_X4(bV, buf + OFF11_B + offB);
#pragma unroll
                for (int mb = 0; mb < 2; mb++) {
                    mma_f16(acc[mb][nb * 2 + 0], aV[mb], bV[0], bV[1]);
                    mma_f16(acc[mb][nb * 2 + 1], aV[mb], bV[2], bV[3]);
                }
            }
        }
        stage = (stage == 2) ? 0 : stage + 1;
        pstage = (pstage == 2) ? 0 : pstage + 1;
    }
    __syncthreads();
#undef ISSUE_STAGE11
}

// Epilogue coordinates: acc[mb][j][reg]
//   row_local = wm*32 + mb*16 + (lane>>2) + (reg>=2)*8
//   col_local = wn*64 + j*8 + (lane&3)*2 + (reg&1)

// ---------------------------------------------------------------------------
// Kernel: input conversions. sel: 0=hidden(bf16 split), 1..3=wq,wk,wv(bf16
// split), 4=wo(fp16 single)
// ---------------------------------------------------------------------------
__global__ void __launch_bounds__(256)
k_convert(const float* __restrict__ in, int sel, long n4) {
    long i = (long)blockIdx.x * blockDim.x + threadIdx.x;
    if (i >= n4) return;
    float4 v = ((const float4*)in)[i];
    if (sel == 4) {
        alignas(8) fp16 h[4];
        h[0] = __float2half(v.x); h[1] = __float2half(v.y);
        h[2] = __float2half(v.z); h[3] = __float2half(v.w);
        *(uint2*)(g_Wo16 + i * 4) = *(const uint2*)h;
        return;
    }
    bf16 *H, *M;
    if (sel == 0) { H = g_Hh; M = g_Hm; }
    else          { H = g_Wh3[sel - 1]; M = g_Wm3[sel - 1]; }
    alignas(8) bf16 h[4], m[4];
    split_bf16(v.x, h[0], m[0]);
    split_bf16(v.y, h[1], m[1]);
    split_bf16(v.z, h[2], m[2]);
    split_bf16(v.w, h[3], m[3]);
    *(uint2*)(H + i * 4) = *(const uint2*)h;
    *(uint2*)(M + i * 4) = *(const uint2*)m;
}

// ---------------------------------------------------------------------------
// Kernel: Q/K/V projection (bf16 3-split GEMM for all three; epilogue
// differs: Q,K -> bf16 splits, V -> single fp16). grid (nt, mt, which=3).
// ---------------------------------------------------------------------------
__global__ void __launch_bounds__(256, 2)
k_proj(void) {
    extern __shared__ char sm[];
    const uint32_t sb = smem_u32(sm);
    const int nt = blockIdx.x, mt = blockIdx.y, which = blockIdx.z;

    float acc[2][8][4];
    gemm_mainloop(sb,
        g_Hh + (size_t)mt * 128 * DM, g_Hm + (size_t)mt * 128 * DM, DM,
        g_Wh3[which] + (size_t)nt * 128 * DM, g_Wm3[which] + (size_t)nt * 128 * DM, DM,
        DM / 32, acc);

    const int tid = threadIdx.x, lane = tid & 31, wid = tid >> 5;
    const int wm = wid >> 1, wn = wid & 1;

    if (which == 2) {  // V -> single fp16
#pragma unroll
        for (int mb = 0; mb < 2; mb++)
#pragma unroll
            for (int rp = 0; rp < 2; rp++) {
                const int m = mt * 128 + wm * 32 + mb * 16 + (lane >> 2) + rp * 8;
                const int b = m >> 11, s = m & (SEQ - 1);
                fp16* pv = g_V16 + ((size_t)(b * NH + nt) * SEQ + s) * DH;
#pragma unroll
                for (int j = 0; j < 8; j++) {
                    const int col = wn * 64 + j * 8 + (lane & 3) * 2;
                    __half2 hv = __floats2half2_rn(acc[mb][j][rp * 2 + 0],
                                                   acc[mb][j][rp * 2 + 1]);
                    *(__half2*)(pv + col) = hv;
                }
            }
        return;
    }

    bf16* Gh = (which == 0) ? g_Qh : g_Kh;
    bf16* Gm = (which == 0) ? g_Qm : g_Km;
#pragma unroll
    for (int mb = 0; mb < 2; mb++)
#pragma unroll
        for (int rp = 0; rp < 2; rp++) {
            const int m = mt * 128 + wm * 32 + mb * 16 + (lane >> 2) + rp * 8;
            const int b = m >> 11, s = m & (SEQ - 1);
            bf16* ph = Gh + ((size_t)(b * NH + nt) * SEQ + s) * DH;
            bf16* pm = Gm + ((size_t)(b * NH + nt) * SEQ + s) * DH;
#pragma unroll
            for (int j = 0; j < 8; j++) {
                const int col = wn * 64 + j * 8 + (lane & 3) * 2;
                bf16 h0, m0, h1, m1;
                split_bf16(acc[mb][j][rp * 2 + 0], h0, m0);
                split_bf16(acc[mb][j][rp * 2 + 1], h1, m1);
                *(__nv_bfloat162*)(ph + col) = __nv_bfloat162(h0, h1);
                *(__nv_bfloat162*)(pm + col) = __nv_bfloat162(m0, m1);
            }
        }
}

// ---------------------------------------------------------------------------
// Kernel: transpose V [bh,s,dh] -> [bh,dh,s] (single fp16)
// ---------------------------------------------------------------------------
__global__ void __launch_bounds__(256)
k_transpose() {
    __shared__ fp16 tile[32][33];
    const int d0 = blockIdx.x * 32;
    const int s0 = blockIdx.y * 32;
    const int bh = blockIdx.z;
    const int tx = threadIdx.x, ty = threadIdx.y;
#pragma unroll
    for (int r = 0; r < 4; r++)
        tile[ty + r * 8][tx] =
            g_V16[(size_t)bh * SEQ * DH + (size_t)(s0 + ty + r * 8) * DH + d0 + tx];
    __syncthreads();
#pragma unroll
    for (int r = 0; r < 4; r++)
        g_Vt16[(size_t)bh * DH * SEQ + (size_t)(d0 + ty + r * 8) * SEQ + s0 + tx] =
            tile[tx][ty + r * 8];
}

// ---------------------------------------------------------------------------
// Kernel: causal scores = Q . K^T (fp32 to g_S). Triangular launch.
// ---------------------------------------------------------------------------
__global__ void __launch_bounds__(256, 2)
k_scores() {
    const int t = blockIdx.x;
    int bi = (int)((sqrtf(8.f * (float)t + 1.f) - 1.f) * 0.5f);
    if ((bi + 1) * (bi + 2) / 2 <= t) bi++;
    else if (bi * (bi + 1) / 2 > t) bi--;
    const int bj = t - bi * (bi + 1) / 2;
    const int bh = blockIdx.y;

    extern __shared__ char sm[];
    const uint32_t sb = smem_u32(sm);

    const size_t hb = (size_t)bh * SEQ * DH;
    float acc[2][8][4];
    gemm_mainloop(sb,
        g_Qh + hb + (size_t)bi * 128 * DH, g_Qm + hb + (size_t)bi * 128 * DH, DH,
        g_Kh + hb + (size_t)bj * 128 * DH, g_Km + hb + (size_t)bj * 128 * DH, DH,
        DH / 32, acc);

    const int tid = threadIdx.x, lane = tid & 31, wid = tid >> 5;
    const int wm = wid >> 1, wn = wid & 1;
    float* Sp = g_S + (size_t)bh * SEQ * SEQ;
#pragma unroll
    for (int mb = 0; mb < 2; mb++)
#pragma unroll
        for (int rp = 0; rp < 2; rp++) {
            const int m = bi * 128 + wm * 32 + mb * 16 + (lane >> 2) + rp * 8;
            float* dst = Sp + (size_t)m * SEQ + bj * 128;
#pragma unroll
            for (int j = 0; j < 8; j++) {
                const int col = wn * 64 + j * 8 + (lane & 3) * 2;
                *(float2*)(dst + col) =
                    make_float2(acc[mb][j][rp * 2], acc[mb][j][rp * 2 + 1]);
            }
        }
}

// ---------------------------------------------------------------------------
// Kernel: row softmax (vectorized, 8 contiguous cols/thread). Skips loads
// entirely beyond the causal boundary. In-place SINGLE fp16 probs into the
// g_S row; fp32 probs to Pext when use_ext.
// ---------------------------------------------------------------------------
__device__ __forceinline__ float warp_max(float v) {
#pragma unroll
    for (int o = 16; o > 0; o >>= 1) v = fmaxf(v, __shfl_xor_sync(0xffffffffu, v, o));
    return v;
}
__device__ __forceinline__ float warp_sum(float v) {
#pragma unroll
    for (int o = 16; o > 0; o >>= 1) v += __shfl_xor_sync(0xffffffffu, v, o);
    return v;
}

__global__ void __launch_bounds__(256)
k_softmax(float* __restrict__ Pext, int use_ext) {
    __shared__ float shm[8];
    __shared__ float shs[8];

    const size_t row = blockIdx.x;
    const int q = (int)(row & (SEQ - 1));
    const float* pr = g_S + row * (size_t)SEQ;
    const int tid = threadIdx.x;
    const int wid = tid >> 5, lid = tid & 31;
    const int jb = tid * 8;

    float v[8];
    if (jb <= q) {
        float4 a = *(const float4*)(pr + jb);
        float4 b = *(const float4*)(pr + jb + 4);
        v[0] = a.x; v[1] = a.y; v[2] = a.z; v[3] = a.w;
        v[4] = b.x; v[5] = b.y; v[6] = b.z; v[7] = b.w;
#pragma unroll
        for (int k = 0; k < 8; k++)
            if (jb + k > q) v[k] = -CUDART_INF_F;
    } else {
#pragma unroll
        for (int k = 0; k < 8; k++) v[k] = -CUDART_INF_F;
    }
    float m = -CUDART_INF_F;
#pragma unroll
    for (int k = 0; k < 8; k++) m = fmaxf(m, v[k]);
    m = warp_max(m);
    if (lid == 0) shm[wid] = m;
    __syncthreads();          // all row reads precede in-place writes
    if (tid < 32) {
        float t = (tid < 8) ? shm[tid] : -CUDART_INF_F;
        t = warp_max(t);
        if (tid == 0) shm[0] = t;
    }
    __syncthreads();
    m = shm[0];

    float s = 0.f;
#pragma unroll
    for (int k = 0; k < 8; k++) {
        const float e = expf(v[k] - m);
        v[k] = e;
        s += e;
    }
    s = warp_sum(s);
    if (lid == 0) shs[wid] = s;
    __syncthreads();
    if (tid < 32) {
        float t = (tid < 8) ? shs[tid] : 0.f;
        t = warp_sum(t);
        if (tid == 0) shs[0] = t;
    }
    __syncthreads();
    const float inv = 1.f / shs[0];

#pragma unroll
    for (int k = 0; k < 8; k++) v[k] *= inv;

    if (use_ext) {
        float* po = Pext + row * (size_t)SEQ + jb;
        *(float4*)(po)     = make_float4(v[0], v[1], v[2], v[3]);
        *(float4*)(po + 4) = make_float4(v[4], v[5], v[6], v[7]);
    }

    const int jmax = ((q >> 7) + 1) << 7;      // 128-aligned
    if (jb < jmax) {
        fp16* ph = (fp16*)(g_S) + row * (size_t)(2 * SEQ) + jb;  // row = 8KB
        alignas(16) fp16 h[8];
#pragma unroll
        for (int k = 0; k < 8; k++) h[k] = __float2half(v[k]);
        *(uint4*)ph = *(const uint4*)h;
    }
}

// ---------------------------------------------------------------------------
// Kernel: AV = P . V (fp16 single x single, causal-truncated).
// grid (bh=64, ybi=16), longest-first. Epilogue: single fp16 into g_AO16.
// ---------------------------------------------------------------------------
__global__ void __launch_bounds__(256, 2)
k_av() {
    const int bh = blockIdx.x;
    const int bi = 15 - (int)blockIdx.y;
    extern __shared__ char sm[];
    const uint32_t sb = smem_u32(sm);

    const fp16* Pbase = (const fp16*)(g_S) +
                        (size_t)(bh * SEQ + bi * 128) * (size_t)(2 * SEQ);

    float acc[2][8][4];
    gemm_mainloop_11(sb,
        Pbase, 2 * SEQ,
        g_Vt16 + (size_t)bh * DH * SEQ, SEQ,
        (bi + 1) * 4, acc);

    const int tid = threadIdx.x, lane = tid & 31, wid = tid >> 5;
    const int wm = wid >> 1, wn = wid & 1;
    const int b = bh >> 4, h = bh & 15;
#pragma unroll
    for (int mb = 0; mb < 2; mb++)
#pragma unroll
        for (int rp = 0; rp < 2; rp++) {
            const int s = bi * 128 + wm * 32 + mb * 16 + (lane >> 2) + rp * 8;
            fp16* po = g_AO16 + ((size_t)(b * SEQ + s)) * DM + h * 128;
#pragma unroll
            for (int j = 0; j < 8; j++) {
                const int col = wn * 64 + j * 8 + (lane & 3) * 2;
                __half2 hv = __floats2half2_rn(acc[mb][j][rp * 2 + 0],
                                               acc[mb][j][rp * 2 + 1]);
                *(__half2*)(po + col) = hv;
            }
        }
}

// ---------------------------------------------------------------------------
// Kernel: out = AO . Wo^T + bo (fp16 single x single, fp32 to d_out).
// ---------------------------------------------------------------------------
__global__ void __launch_bounds__(256, 2)
k_out(const float* __restrict__ bias, float* __restrict__ Out) {
    extern __shared__ char sm[];
    const uint32_t sb = smem_u32(sm);
    const int nt = blockIdx.x, mt = blockIdx.y;

    float acc[2][8][4];
    gemm_mainloop_11(sb,
        g_AO16 + (size_t)mt * 128 * DM, DM,
        g_Wo16 + (size_t)nt * 128 * DM, DM,
        DM / 32, acc);

    const int tid = threadIdx.x, lane = tid & 31, wid = tid >> 5;
    const int wm = wid >> 1, wn = wid & 1;
#pragma unroll
    for (int mb = 0; mb < 2; mb++)
#pragma unroll
        for (int rp = 0; rp < 2; rp++) {
            const int m = mt * 128 + wm * 32 + mb * 16 + (lane >> 2) + rp * 8;
            float* dst = Out + (size_t)m * DM + nt * 128;
#pragma unroll
            for (int j = 0; j < 8; j++) {
                const int col = wn * 64 + j * 8 + (lane & 3) * 2;
                *(float2*)(dst + col) =
                    make_float2(acc[mb][j][rp * 2] + bias[nt * 128 + col],
                                acc[mb][j][rp * 2 + 1] + bias[nt * 128 + col + 1]);
            }
        }
}

// ---------------------------------------------------------------------------
// Launch
// ---------------------------------------------------------------------------
extern "C" void kernel_launch(void* const* d_in, const int* in_sizes, int n_in,
                              void* d_out, int out_size) {
    const float* hs = (const float*)d_in[0];
    const float* wq = (const float*)d_in[1];
    const float* wk = (const float*)d_in[2];
    const float* wv = (const float*)d_in[3];
    const float* wo = (const float*)d_in[4];
    const float* bo = (const float*)d_in[5];
    float* out = (float*)d_out;

    const long long OUT_ELEMS = (long long)MROWS * DM;       // 16,777,216
    const long long WEI_ELEMS = (long long)BH * SEQ * SEQ;   // 268,435,456
    const int use_ext = ((long long)out_size >= OUT_ELEMS + WEI_ELEMS) ? 1 : 0;
    float* Pext = use_ext ? (out + OUT_ELEMS) : nullptr;

    cudaFuncSetAttribute(k_proj,   cudaFuncAttributeMaxDynamicSharedMemorySize, SMEM_GEMM);
    cudaFuncSetAttribute(k_scores, cudaFuncAttributeMaxDynamicSharedMemorySize, SMEM_GEMM);
    cudaFuncSetAttribute(k_av,     cudaFuncAttributeMaxDynamicSharedMemorySize, SMEM_GEMM11);
    cudaFuncSetAttribute(k_out,    cudaFuncAttributeMaxDynamicSharedMemorySize, SMEM_GEMM11);

    const long nH4 = (long)MROWS * DM / 4;
    const long nW4 = (long)DM * DM / 4;
    k_convert<<<(unsigned)((nH4 + 255) / 256), 256>>>(hs, 0, nH4);
    k_convert<<<(unsigned)((nW4 + 255) / 256), 256>>>(wq, 1, nW4);
    k_convert<<<(unsigned)((nW4 + 255) / 256), 256>>>(wk, 2, nW4);
    k_convert<<<(unsigned)((nW4 + 255) / 256), 256>>>(wv, 3, nW4);
    k_convert<<<(unsigned)((nW4 + 255) / 256), 256>>>(wo, 4, nW4);

    k_proj<<<dim3(16, 64, 3), 256, SMEM_GEMM>>>();

    k_transpose<<<dim3(4, 64, BH), dim3(32, 8)>>>();

    k_scores<<<dim3(136, BH), 256, SMEM_GEMM>>>();
    k_softmax<<<BH * SEQ, 256>>>(Pext, use_ext);
    k_av<<<dim3(BH, 16), 256, SMEM_GEMM11>>>();
    k_out<<<dim3(16, 64), 256, SMEM_GEMM11>>>(bo, out);
}